// round 5
// baseline (speedup 1.0000x reference)
#include <cuda_runtime.h>
#include <cuda_bf16.h>
#include <math.h>

typedef unsigned long long ull;

// ---------------- problem constants ----------------
#define BB 64
#define SS 8
#define TT 8192
#define L1_LEN 8190   // after dil-1 conv
#define L2_LEN 8184   // after dil-3 conv
#define L3_LEN 8166   // after dil-9 conv

// ---------------- packed f32x2 helpers ----------------
__device__ __forceinline__ ull pk2(float lo, float hi) {
    ull r; asm("mov.b64 %0, {%1, %2};" : "=l"(r) : "f"(lo), "f"(hi)); return r;
}
__device__ __forceinline__ void up2(ull v, float& lo, float& hi) {
    asm("mov.b64 {%0, %1}, %2;" : "=f"(lo), "=f"(hi) : "l"(v));
}
__device__ __forceinline__ void fma2(ull& d, ull a, ull b) {
    asm("fma.rn.f32x2 %0, %1, %2, %0;" : "+l"(d) : "l"(a), "l"(b));
}

// ---------------- device scratch ----------------
__device__ float g_x0[(size_t)BB * 8  * TT];   // eeg after 1x1 head
__device__ float g_x3[(size_t)BB * 16 * TT];   // eeg final features
__device__ float g_nx[BB * 16];
__device__ float g_nst2[BB * SS * 16];
__device__ float g_dot[(size_t)BB * SS * 256];

// ---------------- kernel 1: eeg 1x1 head (64 -> 8) ----------------
__global__ void k_head(const float* __restrict__ eeg,
                       const float* __restrict__ w,      // [8][64]
                       const float* __restrict__ bias)   // [8]
{
    __shared__ float sh_w[512];
    __shared__ float sh_b[8];
    int tid = threadIdx.x;
    for (int i = tid; i < 512; i += 256) sh_w[i] = w[i];
    if (tid < 8) sh_b[tid] = bias[tid];
    __syncthreads();

    size_t idx = (size_t)blockIdx.x * 256 + tid;
    int b = (int)(idx >> 13);
    int t = (int)(idx & (TT - 1));

    const float4* ep = (const float4*)(eeg + idx * 64);
    float acc[8];
#pragma unroll
    for (int c = 0; c < 8; c++) acc[c] = sh_b[c];
#pragma unroll
    for (int q = 0; q < 16; q++) {
        float4 v = ep[q];
#pragma unroll
        for (int c = 0; c < 8; c++) {
            acc[c] += v.x * sh_w[c * 64 + q * 4 + 0]
                    + v.y * sh_w[c * 64 + q * 4 + 1]
                    + v.z * sh_w[c * 64 + q * 4 + 2]
                    + v.w * sh_w[c * 64 + q * 4 + 3];
        }
    }
    float* ob = g_x0 + ((size_t)b * 8) * TT + t;
#pragma unroll
    for (int c = 0; c < 8; c++) ob[(size_t)c * TT] = acc[c];
}

// ---------------- packed conv layer body (shared -> shared) ----------------
template <int CIN, int DIL>
__device__ __forceinline__ void conv_layer_s(const float* __restrict__ src, int sp,
                                             float* __restrict__ dst, int dp,
                                             const float* __restrict__ w,
                                             const ull* __restrict__ bp,
                                             int len, int tid)
{
    int items = 4 * ((len + 3) >> 2);
#pragma unroll 1
    for (int it = tid; it < items; it += 256) {
        int cg = it & 3;
        int p  = (it >> 2) * 4;
        ull b01 = bp[cg * 2], b23 = bp[cg * 2 + 1];
        ull a0[4], a1[4];
#pragma unroll
        for (int t = 0; t < 4; t++) { a0[t] = b01; a1[t] = b23; }
#pragma unroll
        for (int ci = 0; ci < CIN; ci++) {
#pragma unroll
            for (int k = 0; k < 3; k++) {
                const ull* wp = (const ull*)&w[(ci * 3 + k) * 16 + cg * 4];
                ull w01 = wp[0], w23 = wp[1];
                const float* xr = &src[ci * sp + p + k * DIL];
#pragma unroll
                for (int t = 0; t < 4; t++) {
                    ull x2 = pk2(xr[t], xr[t]);
                    fma2(a0[t], w01, x2);
                    fma2(a1[t], w23, x2);
                }
            }
        }
        int c0 = cg * 4;
#pragma unroll
        for (int t = 0; t < 4; t++) {
            if (p + t < len) {
                float l, h;
                up2(a0[t], l, h);
                dst[(c0 + 0) * dp + p + t] = fmaxf(l, 0.f);
                dst[(c0 + 1) * dp + p + t] = fmaxf(h, 0.f);
                up2(a1[t], l, h);
                dst[(c0 + 2) * dp + p + t] = fmaxf(l, 0.f);
                dst[(c0 + 3) * dp + p + t] = fmaxf(h, 0.f);
            }
        }
    }
}

// ---------------- kernel 2: fused eeg dilated stack (8->16->16->16) ----------------
#define EP1 284   // l1 pitch
#define EP2 284   // input/l2 pitch (input needs >= 282)
__global__ void __launch_bounds__(256, 2)
k_eeg_stack(const float* __restrict__ w1, const float* __restrict__ b1,
            const float* __restrict__ w2, const float* __restrict__ b2,
            const float* __restrict__ w3, const float* __restrict__ b3)
{
    __shared__ __align__(16) float sA[16 * EP1];      // l1
    __shared__ __align__(16) float sB[16 * EP2];      // input (8 rows), then l2 (16 rows)
    __shared__ __align__(16) float sw1[384], sw2[768], sw3[768];
    __shared__ ull bp1[8], bp2[8], bp3[8];

    int b  = blockIdx.y;
    int t0 = blockIdx.x * 256;
    int tid = threadIdx.x;
    int nOut = min(256, L3_LEN - t0);
    int n2 = nOut + 18, n1 = nOut + 24, nIn = nOut + 26;

    for (int i = tid; i < 384; i += 256) {
        int co = i & 15; int rem = i >> 4; int k = rem % 3; int ci = rem / 3;
        sw1[i] = w1[(co * 8 + ci) * 3 + k];
    }
    for (int i = tid; i < 768; i += 256) {
        int co = i & 15; int rem = i >> 4; int k = rem % 3; int ci = rem / 3;
        sw2[i] = w2[(co * 16 + ci) * 3 + k];
        sw3[i] = w3[(co * 16 + ci) * 3 + k];
    }
    if (tid < 8) {
        bp1[tid] = pk2(b1[2 * tid], b1[2 * tid + 1]);
        bp2[tid] = pk2(b2[2 * tid], b2[2 * tid + 1]);
        bp3[tid] = pk2(b3[2 * tid], b3[2 * tid + 1]);
    }

    // stage input (8 ch) into sB
    const float* inb = g_x0 + ((size_t)b * 8) * TT + t0;
    for (int i = tid; i < 8 * nIn; i += 256) {
        int ci = i / nIn, q = i - ci * nIn;
        sB[ci * EP2 + q] = (t0 + q < TT) ? inb[(size_t)ci * TT + q] : 0.f;
    }
    __syncthreads();

    // layer1: 8 -> 16, dil 1   (sB input -> sA)
    conv_layer_s<8, 1>(sB, EP2, sA, EP1, sw1, bp1, n1, tid);
    __syncthreads();

    // layer2: 16 -> 16, dil 3  (sA -> sB, overwrites dead input)
    conv_layer_s<16, 3>(sA, EP1, sB, EP2, sw2, bp2, n2, tid);
    __syncthreads();

    // layer3: 16 -> 16, dil 9  (sB -> global g_x3)
    {
        float* ob = g_x3 + ((size_t)b * 16) * TT + t0;
        int items = 4 * ((nOut + 3) >> 2);
#pragma unroll 1
        for (int it = tid; it < items; it += 256) {
            int cg = it & 3;
            int p  = (it >> 2) * 4;
            ull b01 = bp3[cg * 2], b23 = bp3[cg * 2 + 1];
            ull a0[4], a1[4];
#pragma unroll
            for (int t = 0; t < 4; t++) { a0[t] = b01; a1[t] = b23; }
#pragma unroll
            for (int ci = 0; ci < 16; ci++) {
#pragma unroll
                for (int k = 0; k < 3; k++) {
                    const ull* wp = (const ull*)&sw3[(ci * 3 + k) * 16 + cg * 4];
                    ull w01 = wp[0], w23 = wp[1];
                    const float* xr = &sB[ci * EP2 + p + k * 9];
#pragma unroll
                    for (int t = 0; t < 4; t++) {
                        ull x2 = pk2(xr[t], xr[t]);
                        fma2(a0[t], w01, x2);
                        fma2(a1[t], w23, x2);
                    }
                }
            }
            float lo[4], hi[4], lo2[4], hi2[4];
#pragma unroll
            for (int t = 0; t < 4; t++) { up2(a0[t], lo[t], hi[t]); up2(a1[t], lo2[t], hi2[t]); }
            int c0 = cg * 4;
            if (p + 3 < nOut) {
                *(float4*)&ob[(size_t)(c0 + 0) * TT + p] =
                    make_float4(fmaxf(lo[0],0.f), fmaxf(lo[1],0.f), fmaxf(lo[2],0.f), fmaxf(lo[3],0.f));
                *(float4*)&ob[(size_t)(c0 + 1) * TT + p] =
                    make_float4(fmaxf(hi[0],0.f), fmaxf(hi[1],0.f), fmaxf(hi[2],0.f), fmaxf(hi[3],0.f));
                *(float4*)&ob[(size_t)(c0 + 2) * TT + p] =
                    make_float4(fmaxf(lo2[0],0.f), fmaxf(lo2[1],0.f), fmaxf(lo2[2],0.f), fmaxf(lo2[3],0.f));
                *(float4*)&ob[(size_t)(c0 + 3) * TT + p] =
                    make_float4(fmaxf(hi2[0],0.f), fmaxf(hi2[1],0.f), fmaxf(hi2[2],0.f), fmaxf(hi2[3],0.f));
            } else {
                for (int t = 0; t < 4; t++) {
                    if (p + t < nOut) {
                        ob[(size_t)(c0 + 0) * TT + p + t] = fmaxf(lo[t],  0.f);
                        ob[(size_t)(c0 + 1) * TT + p + t] = fmaxf(hi[t],  0.f);
                        ob[(size_t)(c0 + 2) * TT + p + t] = fmaxf(lo2[t], 0.f);
                        ob[(size_t)(c0 + 3) * TT + p + t] = fmaxf(hi2[t], 0.f);
                    }
                }
            }
        }
    }
}

// ---------------- kernel 3: eeg row norms ----------------
__global__ void k_eegnorm()
{
    __shared__ float red[256];
    int r = blockIdx.x;
    int tid = threadIdx.x;
    const float* p = g_x3 + (size_t)r * TT;
    float ss = 0.f;
    for (int t = tid; t < L3_LEN; t += 256) { float v = p[t]; ss += v * v; }
    red[tid] = ss; __syncthreads();
    for (int st = 128; st > 0; st >>= 1) {
        if (tid < st) red[tid] += red[tid + st];
        __syncthreads();
    }
    if (tid == 0) g_nx[r] = fmaxf(sqrtf(red[0]), 1e-8f);
}

// ---------------- kernel 4: zero accumulators ----------------
__global__ void k_zero()
{
    int i = blockIdx.x * 256 + threadIdx.x;
    if (i < BB * SS * 256) g_dot[i] = 0.f;
    if (i < BB * SS * 16)  g_nst2[i] = 0.f;
}

// ---------------- kernel 5: fused stimulus stack + dot + sumsq ----------------
#define P1 284   // l1 pitch
#define P2 280   // l2 pitch
#define P3 260   // l3 / x pitch
__global__ void __launch_bounds__(256, 2)
k_stim(const float* __restrict__ stim,
       const float* __restrict__ ws1, const float* __restrict__ bs1,
       const float* __restrict__ ws2, const float* __restrict__ bs2,
       const float* __restrict__ ws3, const float* __restrict__ bs3)
{
    __shared__ __align__(16) float bufA[16 * P1];   // l1, then l3, then partials
    __shared__ __align__(16) float bufB[16 * P2];   // l2, then eeg x
    __shared__ __align__(16) float sh_in[P1];
    __shared__ __align__(16) float sh_w2[768];
    __shared__ __align__(16) float sh_w3[768];
    __shared__ float sh_w1[48];
    __shared__ ull sh_bp2[8], sh_bp3[8];
    __shared__ float sh_b1[16];

    int n  = blockIdx.y;          // n = s*B + b
    int s  = n >> 6;
    int b  = n & 63;
    int t0 = blockIdx.x * 256;
    int tid = threadIdx.x;
    int nOut = min(256, L3_LEN - t0);
    int n1 = nOut + 24, n2 = nOut + 18, nIn = nOut + 26;

    if (tid < 48) { int co = tid & 15, k = tid >> 4; sh_w1[k * 16 + co] = ws1[co * 3 + k]; }
    for (int i = tid; i < 768; i += 256) {
        int co = i & 15; int rem = i >> 4; int k = rem % 3; int ci = rem / 3;
        sh_w2[i] = ws2[(co * 16 + ci) * 3 + k];
        sh_w3[i] = ws3[(co * 16 + ci) * 3 + k];
    }
    if (tid < 8) {
        sh_bp2[tid] = pk2(bs2[2 * tid], bs2[2 * tid + 1]);
        sh_bp3[tid] = pk2(bs3[2 * tid], bs3[2 * tid + 1]);
    }
    if (tid < 16) sh_b1[tid] = bs1[tid];

    const float* inb = stim + ((size_t)(b * SS + s)) * TT + t0;
    for (int i = tid; i < nIn; i += 256) sh_in[i] = inb[i];
    __syncthreads();

    // ---- layer 1: 1 -> 16, dil 1 ----
#pragma unroll 1
    for (int it = tid; it < 16 * n1; it += 256) {
        int c = it & 15, q = it >> 4;
        float acc = sh_b1[c];
        acc += sh_in[q + 0] * sh_w1[ 0 + c];
        acc += sh_in[q + 1] * sh_w1[16 + c];
        acc += sh_in[q + 2] * sh_w1[32 + c];
        bufA[c * P1 + q] = fmaxf(acc, 0.f);
    }
    __syncthreads();

    // ---- layer 2: 16 -> 16, dil 3 ----
    conv_layer_s<16, 3>(bufA, P1, bufB, P2, sh_w2, sh_bp2, n2, tid);
    __syncthreads();

    // ---- layer 3: 16 -> 16, dil 9 (bufB -> bufA with pitch P3) ----
    conv_layer_s<16, 9>(bufB, P2, bufA, P3, sh_w3, sh_bp3, nOut, tid);
    __syncthreads();

    // ---- load eeg x tile into bufB ----
    {
        const float* xb = g_x3 + ((size_t)b * 16) * TT + t0;
#pragma unroll
        for (int j = 0; j < 16; j++)
            if (tid < nOut) bufB[j * P3 + tid] = xb[(size_t)j * TT + tid];
    }
    __syncthreads();

    // ---- dot phase: 2x2 register tile, 4 t-chunks ----
    int chunk = tid >> 6;
    int q = tid & 63;
    int ip = q >> 3, jp = q & 7;
    int i0 = ip * 2, j0 = jp * 2;
    const ull* A0 = (const ull*)(bufA + (i0 + 0) * P3);
    const ull* A1 = (const ull*)(bufA + (i0 + 1) * P3);
    const ull* B0 = (const ull*)(bufB + (j0 + 0) * P3);
    const ull* B1 = (const ull*)(bufB + (j0 + 1) * P3);
    int tBeg = chunk * 64;
    int tEnd = min(tBeg + 64, nOut);
    ull c00 = 0, c01 = 0, c10 = 0, c11 = 0, ss0 = 0, ss1 = 0;
#pragma unroll 1
    for (int t2 = tBeg >> 1; t2 < (tEnd >> 1); t2++) {
        ull a0 = A0[t2], a1 = A1[t2], b0 = B0[t2], b1 = B1[t2];
        fma2(c00, a0, b0); fma2(c01, a0, b1);
        fma2(c10, a1, b0); fma2(c11, a1, b1);
        if (jp == 0) { fma2(ss0, a0, a0); fma2(ss1, a1, a1); }
    }
    __syncthreads();   // all l3/x reads done before bufA reuse

    {
        float l, h;
        float* part = bufA;
        up2(c00, l, h); part[chunk * 256 + (i0 + 0) * 16 + j0 + 0] = l + h;
        up2(c01, l, h); part[chunk * 256 + (i0 + 0) * 16 + j0 + 1] = l + h;
        up2(c10, l, h); part[chunk * 256 + (i0 + 1) * 16 + j0 + 0] = l + h;
        up2(c11, l, h); part[chunk * 256 + (i0 + 1) * 16 + j0 + 1] = l + h;
        if (jp == 0) {
            up2(ss0, l, h); part[1024 + chunk * 16 + i0 + 0] = l + h;
            up2(ss1, l, h); part[1024 + chunk * 16 + i0 + 1] = l + h;
        }
    }
    __syncthreads();

    float d = bufA[tid] + bufA[256 + tid] + bufA[512 + tid] + bufA[768 + tid];
    atomicAdd(&g_dot[(size_t)n * 256 + tid], d);
    if (tid < 16) {
        float sv = bufA[1024 + tid] + bufA[1024 + 16 + tid]
                 + bufA[1024 + 32 + tid] + bufA[1024 + 48 + tid];
        atomicAdd(&g_nst2[n * 16 + tid], sv);
    }
}

// ---------------- kernel 6: finalize ----------------
__global__ void k_final(const float* __restrict__ w_lin,
                        const float* __restrict__ b_lin,
                        float* __restrict__ out)
{
    __shared__ float red[256];
    int n = blockIdx.x;
    int s = n >> 6;
    int b = n & 63;
    int tid = threadIdx.x;
    int i = tid >> 4, j = tid & 15;

    float ni = fmaxf(sqrtf(g_nst2[n * 16 + i]), 1e-8f);
    float nj = g_nx[b * 16 + j];
    float v  = w_lin[tid] * g_dot[(size_t)n * 256 + tid] / (ni * nj);

    red[tid] = v; __syncthreads();
    for (int st = 128; st > 0; st >>= 1) {
        if (tid < st) red[tid] += red[tid + st];
        __syncthreads();
    }
    if (tid == 0) out[b * SS + s] = red[0] + b_lin[0];
}

// ---------------- launch ----------------
extern "C" void kernel_launch(void* const* d_in, const int* in_sizes, int n_in,
                              void* d_out, int out_size)
{
    const float* eeg   = (const float*)d_in[0];
    const float* stim  = (const float*)d_in[1];
    const float* w_eeg = (const float*)d_in[2];
    const float* b_eeg = (const float*)d_in[3];
    const float* w_e1  = (const float*)d_in[4];
    const float* b_e1  = (const float*)d_in[5];
    const float* w_e2  = (const float*)d_in[6];
    const float* b_e2  = (const float*)d_in[7];
    const float* w_e3  = (const float*)d_in[8];
    const float* b_e3  = (const float*)d_in[9];
    const float* w_s1  = (const float*)d_in[10];
    const float* b_s1  = (const float*)d_in[11];
    const float* w_s2  = (const float*)d_in[12];
    const float* b_s2  = (const float*)d_in[13];
    const float* w_s3  = (const float*)d_in[14];
    const float* b_s3  = (const float*)d_in[15];
    const float* w_lin = (const float*)d_in[16];
    const float* b_lin = (const float*)d_in[17];
    float* out = (float*)d_out;

    k_head<<<(BB * TT) / 256, 256>>>(eeg, w_eeg, b_eeg);
    k_eeg_stack<<<dim3(32, BB), 256>>>(w_e1, b_e1, w_e2, b_e2, w_e3, b_e3);
    k_eegnorm<<<BB * 16, 256>>>();

    k_zero<<<(BB * SS * 256) / 256, 256>>>();

    k_stim<<<dim3(32, BB * SS), 256>>>(stim, w_s1, b_s1, w_s2, b_s2, w_s3, b_s3);

    k_final<<<BB * SS, 256>>>(w_lin, b_lin, out);
}

// round 7
// speedup vs baseline: 1.0269x; 1.0269x over previous
#include <cuda_runtime.h>
#include <cuda_bf16.h>
#include <math.h>

typedef unsigned long long ull;

// ---------------- problem constants ----------------
#define BB 64
#define SS 8
#define TT 8192
#define L1_LEN 8190
#define L2_LEN 8184
#define L3_LEN 8166

// ---------------- packed f32x2 helpers ----------------
__device__ __forceinline__ ull pk2(float lo, float hi) {
    ull r; asm("mov.b64 %0, {%1, %2};" : "=l"(r) : "f"(lo), "f"(hi)); return r;
}
__device__ __forceinline__ void up2(ull v, float& lo, float& hi) {
    asm("mov.b64 {%0, %1}, %2;" : "=f"(lo), "=f"(hi) : "l"(v));
}
__device__ __forceinline__ void fma2(ull& d, ull a, ull b) {
    asm("fma.rn.f32x2 %0, %1, %2, %0;" : "+l"(d) : "l"(a), "l"(b));
}

// ---------------- device scratch ----------------
__device__ float g_x0[(size_t)BB * 8  * TT];   // eeg after 1x1 head
__device__ float g_x3[(size_t)BB * 16 * TT];   // eeg final features
__device__ float g_nx[BB * 16];                // eeg norms (sqrt+clamp)

// ---------------- kernel 1: eeg 1x1 head (64 -> 8) ----------------
__global__ void k_head(const float* __restrict__ eeg,
                       const float* __restrict__ w,      // [8][64]
                       const float* __restrict__ bias)   // [8]
{
    __shared__ float sh_w[512];
    __shared__ float sh_b[8];
    int tid = threadIdx.x;
    for (int i = tid; i < 512; i += 256) sh_w[i] = w[i];
    if (tid < 8) sh_b[tid] = bias[tid];
    __syncthreads();

    size_t idx = (size_t)blockIdx.x * 256 + tid;
    int b = (int)(idx >> 13);
    int t = (int)(idx & (TT - 1));

    const float4* ep = (const float4*)(eeg + idx * 64);
    float acc[8];
#pragma unroll
    for (int c = 0; c < 8; c++) acc[c] = sh_b[c];
#pragma unroll
    for (int q = 0; q < 16; q++) {
        float4 v = ep[q];
#pragma unroll
        for (int c = 0; c < 8; c++) {
            acc[c] += v.x * sh_w[c * 64 + q * 4 + 0]
                    + v.y * sh_w[c * 64 + q * 4 + 1]
                    + v.z * sh_w[c * 64 + q * 4 + 2]
                    + v.w * sh_w[c * 64 + q * 4 + 3];
        }
    }
    float* ob = g_x0 + ((size_t)b * 8) * TT + t;
#pragma unroll
    for (int c = 0; c < 8; c++) ob[(size_t)c * TT] = acc[c];
}

// ---------------- packed conv layer body (shared -> shared) ----------------
// NOTE: no unroll-1 pragma — let ptxas software-pipeline (R5 lesson).
template <int CIN, int DIL>
__device__ __forceinline__ void conv_layer_s(const float* __restrict__ src, int sp,
                                             float* __restrict__ dst, int dp,
                                             const float* __restrict__ w,
                                             const ull* __restrict__ bp,
                                             int len, int tid)
{
    int items = 4 * ((len + 3) >> 2);
    for (int it = tid; it < items; it += 256) {
        int cg = it & 3;
        int p  = (it >> 2) * 4;
        ull b01 = bp[cg * 2], b23 = bp[cg * 2 + 1];
        ull a0[4], a1[4];
#pragma unroll
        for (int t = 0; t < 4; t++) { a0[t] = b01; a1[t] = b23; }
#pragma unroll
        for (int ci = 0; ci < CIN; ci++) {
#pragma unroll
            for (int k = 0; k < 3; k++) {
                const ull* wp = (const ull*)&w[(ci * 3 + k) * 16 + cg * 4];
                ull w01 = wp[0], w23 = wp[1];
                const float* xr = &src[ci * sp + p + k * DIL];
#pragma unroll
                for (int t = 0; t < 4; t++) {
                    ull x2 = pk2(xr[t], xr[t]);
                    fma2(a0[t], w01, x2);
                    fma2(a1[t], w23, x2);
                }
            }
        }
        int c0 = cg * 4;
#pragma unroll
        for (int t = 0; t < 4; t++) {
            if (p + t < len) {
                float l, h;
                up2(a0[t], l, h);
                dst[(c0 + 0) * dp + p + t] = fmaxf(l, 0.f);
                dst[(c0 + 1) * dp + p + t] = fmaxf(h, 0.f);
                up2(a1[t], l, h);
                dst[(c0 + 2) * dp + p + t] = fmaxf(l, 0.f);
                dst[(c0 + 3) * dp + p + t] = fmaxf(h, 0.f);
            }
        }
    }
}

// ---------------- kernel 2: fused eeg dilated stack (8->16->16->16) ----------------
#define EP1 284
#define EP2 284
__global__ void __launch_bounds__(256, 2)
k_eeg_stack(const float* __restrict__ w1, const float* __restrict__ b1,
            const float* __restrict__ w2, const float* __restrict__ b2,
            const float* __restrict__ w3, const float* __restrict__ b3)
{
    __shared__ __align__(16) float sA[16 * EP1];      // l1
    __shared__ __align__(16) float sB[16 * EP2];      // input (8 rows), then l2
    __shared__ __align__(16) float sw1[384], sw2[768], sw3[768];
    __shared__ ull bp1[8], bp2[8], bp3[8];

    int b  = blockIdx.y;
    int t0 = blockIdx.x * 256;
    int tid = threadIdx.x;
    int nOut = min(256, L3_LEN - t0);
    int n2 = nOut + 18, n1 = nOut + 24, nIn = nOut + 26;

    for (int i = tid; i < 384; i += 256) {
        int co = i & 15; int rem = i >> 4; int k = rem % 3; int ci = rem / 3;
        sw1[i] = w1[(co * 8 + ci) * 3 + k];
    }
    for (int i = tid; i < 768; i += 256) {
        int co = i & 15; int rem = i >> 4; int k = rem % 3; int ci = rem / 3;
        sw2[i] = w2[(co * 16 + ci) * 3 + k];
        sw3[i] = w3[(co * 16 + ci) * 3 + k];
    }
    if (tid < 8) {
        bp1[tid] = pk2(b1[2 * tid], b1[2 * tid + 1]);
        bp2[tid] = pk2(b2[2 * tid], b2[2 * tid + 1]);
        bp3[tid] = pk2(b3[2 * tid], b3[2 * tid + 1]);
    }

    const float* inb = g_x0 + ((size_t)b * 8) * TT + t0;
    for (int i = tid; i < 8 * nIn; i += 256) {
        int ci = i / nIn, q = i - ci * nIn;
        sB[ci * EP2 + q] = (t0 + q < TT) ? inb[(size_t)ci * TT + q] : 0.f;
    }
    __syncthreads();

    conv_layer_s<8, 1>(sB, EP2, sA, EP1, sw1, bp1, n1, tid);
    __syncthreads();
    conv_layer_s<16, 3>(sA, EP1, sB, EP2, sw2, bp2, n2, tid);
    __syncthreads();

    // layer3 -> global
    {
        float* ob = g_x3 + ((size_t)b * 16) * TT + t0;
        int items = 4 * ((nOut + 3) >> 2);
        for (int it = tid; it < items; it += 256) {
            int cg = it & 3;
            int p  = (it >> 2) * 4;
            ull b01 = bp3[cg * 2], b23 = bp3[cg * 2 + 1];
            ull a0[4], a1[4];
#pragma unroll
            for (int t = 0; t < 4; t++) { a0[t] = b01; a1[t] = b23; }
#pragma unroll
            for (int ci = 0; ci < 16; ci++) {
#pragma unroll
                for (int k = 0; k < 3; k++) {
                    const ull* wp = (const ull*)&sw3[(ci * 3 + k) * 16 + cg * 4];
                    ull w01 = wp[0], w23 = wp[1];
                    const float* xr = &sB[ci * EP2 + p + k * 9];
#pragma unroll
                    for (int t = 0; t < 4; t++) {
                        ull x2 = pk2(xr[t], xr[t]);
                        fma2(a0[t], w01, x2);
                        fma2(a1[t], w23, x2);
                    }
                }
            }
            float lo[4], hi[4], lo2[4], hi2[4];
#pragma unroll
            for (int t = 0; t < 4; t++) { up2(a0[t], lo[t], hi[t]); up2(a1[t], lo2[t], hi2[t]); }
            int c0 = cg * 4;
            if (p + 3 < nOut) {
                *(float4*)&ob[(size_t)(c0 + 0) * TT + p] =
                    make_float4(fmaxf(lo[0],0.f), fmaxf(lo[1],0.f), fmaxf(lo[2],0.f), fmaxf(lo[3],0.f));
                *(float4*)&ob[(size_t)(c0 + 1) * TT + p] =
                    make_float4(fmaxf(hi[0],0.f), fmaxf(hi[1],0.f), fmaxf(hi[2],0.f), fmaxf(hi[3],0.f));
                *(float4*)&ob[(size_t)(c0 + 2) * TT + p] =
                    make_float4(fmaxf(lo2[0],0.f), fmaxf(lo2[1],0.f), fmaxf(lo2[2],0.f), fmaxf(lo2[3],0.f));
                *(float4*)&ob[(size_t)(c0 + 3) * TT + p] =
                    make_float4(fmaxf(hi2[0],0.f), fmaxf(hi2[1],0.f), fmaxf(hi2[2],0.f), fmaxf(hi2[3],0.f));
            } else {
                for (int t = 0; t < 4; t++) {
                    if (p + t < nOut) {
                        ob[(size_t)(c0 + 0) * TT + p + t] = fmaxf(lo[t],  0.f);
                        ob[(size_t)(c0 + 1) * TT + p + t] = fmaxf(hi[t],  0.f);
                        ob[(size_t)(c0 + 2) * TT + p + t] = fmaxf(lo2[t], 0.f);
                        ob[(size_t)(c0 + 3) * TT + p + t] = fmaxf(hi2[t], 0.f);
                    }
                }
            }
        }
    }
}

// ---------------- kernel 3: eeg row norms ----------------
__global__ void k_eegnorm()
{
    __shared__ float red[256];
    int r = blockIdx.x;
    int tid = threadIdx.x;
    const float* p = g_x3 + (size_t)r * TT;
    float ss = 0.f;
    for (int t = tid; t < L3_LEN; t += 256) { float v = p[t]; ss += v * v; }
    red[tid] = ss; __syncthreads();
    for (int st = 128; st > 0; st >>= 1) {
        if (tid < st) red[tid] += red[tid + st];
        __syncthreads();
    }
    if (tid == 0) g_nx[r] = fmaxf(sqrtf(red[0]), 1e-8f);
}

// ---------------- kernel 4: persistent fused stimulus + cosine + linear ----------------
// grid = 512 (one block per n = s*B+b); block 256. Loops all 32 t-tiles,
// dot/sumsq accumulators live in registers; no global atomics, no finalize kernel.
#define P1 284
#define P2 280
#define P3 260
__global__ void __launch_bounds__(256, 2)
k_stim(const float* __restrict__ stim,
       const float* __restrict__ ws1, const float* __restrict__ bs1,
       const float* __restrict__ ws2, const float* __restrict__ bs2,
       const float* __restrict__ ws3, const float* __restrict__ bs3,
       const float* __restrict__ w_lin, const float* __restrict__ b_lin,
       float* __restrict__ out)
{
    __shared__ __align__(16) float bufA[16 * P1];   // l1 / l3 / partials
    __shared__ __align__(16) float bufB[16 * P2];   // l2 / eeg x
    __shared__ __align__(16) float sh_in[P1];
    __shared__ __align__(16) float sh_w2[768];
    __shared__ __align__(16) float sh_w3[768];
    __shared__ float sh_w1[48];
    __shared__ ull sh_bp2[8], sh_bp3[8];
    __shared__ float sh_b1[16];
    __shared__ float sh_wl[256];

    int n  = blockIdx.x;          // n = s*B + b
    int s  = n >> 6;
    int b  = n & 63;
    int tid = threadIdx.x;

    if (tid < 48) { int co = tid & 15, k = tid >> 4; sh_w1[k * 16 + co] = ws1[co * 3 + k]; }
    for (int i = tid; i < 768; i += 256) {
        int co = i & 15; int rem = i >> 4; int k = rem % 3; int ci = rem / 3;
        sh_w2[i] = ws2[(co * 16 + ci) * 3 + k];
        sh_w3[i] = ws3[(co * 16 + ci) * 3 + k];
    }
    if (tid < 8) {
        sh_bp2[tid] = pk2(bs2[2 * tid], bs2[2 * tid + 1]);
        sh_bp3[tid] = pk2(bs3[2 * tid], bs3[2 * tid + 1]);
    }
    if (tid < 16) sh_b1[tid] = bs1[tid];
    sh_wl[tid] = w_lin[tid];

    const float* seq = stim + ((size_t)(b * SS + s)) * TT;
    const float* xbase = g_x3 + ((size_t)b * 16) * TT;

    // dot-phase thread mapping (fixed across tiles)
    int chunk = tid >> 6;
    int q = tid & 63;
    int ip = q >> 3, jp = q & 7;
    int i0 = ip * 2, j0 = jp * 2;
    const ull* A0 = (const ull*)(bufA + (i0 + 0) * P3);
    const ull* A1 = (const ull*)(bufA + (i0 + 1) * P3);
    const ull* B0 = (const ull*)(bufB + (j0 + 0) * P3);
    const ull* B1 = (const ull*)(bufB + (j0 + 1) * P3);

    ull c00 = 0, c01 = 0, c10 = 0, c11 = 0, ss0 = 0, ss1 = 0;

    for (int tile = 0; tile < 32; tile++) {
        int t0 = tile * 256;
        int nOut = min(256, L3_LEN - t0);
        int n1 = nOut + 24, n2 = nOut + 18, nIn = nOut + 26;

        // stage stimulus tile (writes only sh_in; prior dot phase reads only bufA/bufB)
        for (int i = tid; i < nIn; i += 256) sh_in[i] = seq[t0 + i];
        __syncthreads();   // orders: prev dot reads done (bufA safe) + sh_in ready

        // layer 1: 1 -> 16, dil 1
        for (int it = tid; it < 16 * n1; it += 256) {
            int c = it & 15, qq = it >> 4;
            float acc = sh_b1[c];
            acc += sh_in[qq + 0] * sh_w1[ 0 + c];
            acc += sh_in[qq + 1] * sh_w1[16 + c];
            acc += sh_in[qq + 2] * sh_w1[32 + c];
            bufA[c * P1 + qq] = fmaxf(acc, 0.f);
        }
        __syncthreads();

        // layer 2: 16 -> 16, dil 3
        conv_layer_s<16, 3>(bufA, P1, bufB, P2, sh_w2, sh_bp2, n2, tid);
        __syncthreads();

        // layer 3: 16 -> 16, dil 9
        conv_layer_s<16, 9>(bufB, P2, bufA, P3, sh_w3, sh_bp3, nOut, tid);
        __syncthreads();

        // eeg x tile into bufB (l2 dead)
        {
            const float* xb = xbase + t0;
#pragma unroll
            for (int j = 0; j < 16; j++)
                if (tid < nOut) bufB[j * P3 + tid] = xb[(size_t)j * TT + tid];
        }
        __syncthreads();

        // dot accumulate (registers persist across tiles)
        int tBeg = chunk * 64;
        int tEnd = min(tBeg + 64, nOut);
        for (int t2 = tBeg >> 1; t2 < (tEnd >> 1); t2++) {
            ull a0 = A0[t2], a1 = A1[t2], b0 = B0[t2], b1 = B1[t2];
            fma2(c00, a0, b0); fma2(c01, a0, b1);
            fma2(c10, a1, b0); fma2(c11, a1, b1);
            if (jp == 0) { fma2(ss0, a0, a0); fma2(ss1, a1, a1); }
        }
        // no sync here: next iteration's first sync orders dot-reads vs l1 writes
    }
    __syncthreads();   // all dot reads complete before bufA reuse as partials

    // write partials: dot[chunk][i][j], sumsq[chunk][i]
    {
        float l, h;
        float* part = bufA;
        up2(c00, l, h); part[chunk * 256 + (i0 + 0) * 16 + j0 + 0] = l + h;
        up2(c01, l, h); part[chunk * 256 + (i0 + 0) * 16 + j0 + 1] = l + h;
        up2(c10, l, h); part[chunk * 256 + (i0 + 1) * 16 + j0 + 0] = l + h;
        up2(c11, l, h); part[chunk * 256 + (i0 + 1) * 16 + j0 + 1] = l + h;
        if (jp == 0) {
            up2(ss0, l, h); part[1024 + chunk * 16 + i0 + 0] = l + h;
            up2(ss1, l, h); part[1024 + chunk * 16 + i0 + 1] = l + h;
        }
    }
    __syncthreads();

    // cosine + linear, block reduction
    int i = tid >> 4, j = tid & 15;
    float d  = bufA[tid] + bufA[256 + tid] + bufA[512 + tid] + bufA[768 + tid];
    float s2 = bufA[1024 + i] + bufA[1024 + 16 + i]
             + bufA[1024 + 32 + i] + bufA[1024 + 48 + i];
    float ni = fmaxf(sqrtf(s2), 1e-8f);
    float nj = g_nx[b * 16 + j];
    float v  = sh_wl[tid] * d / (ni * nj);
    __syncthreads();

    float* red = bufA + 2048;
    red[tid] = v; __syncthreads();
    for (int st = 128; st > 0; st >>= 1) {
        if (tid < st) red[tid] += red[tid + st];
        __syncthreads();
    }
    if (tid == 0) out[b * SS + s] = red[0] + b_lin[0];
}

// ---------------- launch ----------------
extern "C" void kernel_launch(void* const* d_in, const int* in_sizes, int n_in,
                              void* d_out, int out_size)
{
    const float* eeg   = (const float*)d_in[0];
    const float* stim  = (const float*)d_in[1];
    const float* w_eeg = (const float*)d_in[2];
    const float* b_eeg = (const float*)d_in[3];
    const float* w_e1  = (const float*)d_in[4];
    const float* b_e1  = (const float*)d_in[5];
    const float* w_e2  = (const float*)d_in[6];
    const float* b_e2  = (const float*)d_in[7];
    const float* w_e3  = (const float*)d_in[8];
    const float* b_e3  = (const float*)d_in[9];
    const float* w_s1  = (const float*)d_in[10];
    const float* b_s1  = (const float*)d_in[11];
    const float* w_s2  = (const float*)d_in[12];
    const float* b_s2  = (const float*)d_in[13];
    const float* w_s3  = (const float*)d_in[14];
    const float* b_s3  = (const float*)d_in[15];
    const float* w_lin = (const float*)d_in[16];
    const float* b_lin = (const float*)d_in[17];
    float* out = (float*)d_out;

    k_head<<<(BB * TT) / 256, 256>>>(eeg, w_eeg, b_eeg);
    k_eeg_stack<<<dim3(32, BB), 256>>>(w_e1, b_e1, w_e2, b_e2, w_e3, b_e3);
    k_eegnorm<<<BB * 16, 256>>>();

    k_stim<<<BB * SS, 256>>>(stim, w_s1, b_s1, w_s2, b_s2, w_s3, b_s3,
                             w_lin, b_lin, out);
}

// round 8
// speedup vs baseline: 1.0272x; 1.0003x over previous
#include <cuda_runtime.h>
#include <cuda_bf16.h>
#include <math.h>

typedef unsigned long long ull;

// ---------------- problem constants ----------------
#define BB 64
#define SS 8
#define TT 8192
#define L1_LEN 8190
#define L2_LEN 8184
#define L3_LEN 8166

// ---------------- packed f32x2 helpers ----------------
__device__ __forceinline__ ull pk2(float lo, float hi) {
    ull r; asm("mov.b64 %0, {%1, %2};" : "=l"(r) : "f"(lo), "f"(hi)); return r;
}
__device__ __forceinline__ void up2(ull v, float& lo, float& hi) {
    asm("mov.b64 {%0, %1}, %2;" : "=f"(lo), "=f"(hi) : "l"(v));
}
__device__ __forceinline__ void fma2(ull& d, ull a, ull b) {
    asm("fma.rn.f32x2 %0, %1, %2, %0;" : "+l"(d) : "l"(a), "l"(b));
}

// ---------------- device scratch ----------------
__device__ float g_x0[(size_t)BB * 8  * TT];   // eeg after 1x1 head
__device__ float g_x3[(size_t)BB * 16 * TT];   // eeg final features
__device__ float g_nx[BB * 16];                // eeg norms (sqrt+clamp)

// ---------------- kernel 1: eeg 1x1 head (64 -> 8) ----------------
__global__ void k_head(const float* __restrict__ eeg,
                       const float* __restrict__ w,      // [8][64]
                       const float* __restrict__ bias)   // [8]
{
    __shared__ float sh_w[512];
    __shared__ float sh_b[8];
    int tid = threadIdx.x;
    for (int i = tid; i < 512; i += 256) sh_w[i] = w[i];
    if (tid < 8) sh_b[tid] = bias[tid];
    __syncthreads();

    size_t idx = (size_t)blockIdx.x * 256 + tid;
    int b = (int)(idx >> 13);
    int t = (int)(idx & (TT - 1));

    const float4* ep = (const float4*)(eeg + idx * 64);
    float acc[8];
#pragma unroll
    for (int c = 0; c < 8; c++) acc[c] = sh_b[c];
#pragma unroll
    for (int q = 0; q < 16; q++) {
        float4 v = ep[q];
#pragma unroll
        for (int c = 0; c < 8; c++) {
            acc[c] += v.x * sh_w[c * 64 + q * 4 + 0]
                    + v.y * sh_w[c * 64 + q * 4 + 1]
                    + v.z * sh_w[c * 64 + q * 4 + 2]
                    + v.w * sh_w[c * 64 + q * 4 + 3];
        }
    }
    float* ob = g_x0 + ((size_t)b * 8) * TT + t;
#pragma unroll
    for (int c = 0; c < 8; c++) ob[(size_t)c * TT] = acc[c];
}

// ---------------- packed conv layer body (shared -> shared) ----------------
// NOTE: no unroll-1 pragma — let ptxas software-pipeline (R5 lesson).
template <int CIN, int DIL>
__device__ __forceinline__ void conv_layer_s(const float* __restrict__ src, int sp,
                                             float* __restrict__ dst, int dp,
                                             const float* __restrict__ w,
                                             const ull* __restrict__ bp,
                                             int len, int tid)
{
    int items = 4 * ((len + 3) >> 2);
    for (int it = tid; it < items; it += 256) {
        int cg = it & 3;
        int p  = (it >> 2) * 4;
        ull b01 = bp[cg * 2], b23 = bp[cg * 2 + 1];
        ull a0[4], a1[4];
#pragma unroll
        for (int t = 0; t < 4; t++) { a0[t] = b01; a1[t] = b23; }
#pragma unroll
        for (int ci = 0; ci < CIN; ci++) {
#pragma unroll
            for (int k = 0; k < 3; k++) {
                const ull* wp = (const ull*)&w[(ci * 3 + k) * 16 + cg * 4];
                ull w01 = wp[0], w23 = wp[1];
                const float* xr = &src[ci * sp + p + k * DIL];
#pragma unroll
                for (int t = 0; t < 4; t++) {
                    ull x2 = pk2(xr[t], xr[t]);
                    fma2(a0[t], w01, x2);
                    fma2(a1[t], w23, x2);
                }
            }
        }
        int c0 = cg * 4;
#pragma unroll
        for (int t = 0; t < 4; t++) {
            if (p + t < len) {
                float l, h;
                up2(a0[t], l, h);
                dst[(c0 + 0) * dp + p + t] = fmaxf(l, 0.f);
                dst[(c0 + 1) * dp + p + t] = fmaxf(h, 0.f);
                up2(a1[t], l, h);
                dst[(c0 + 2) * dp + p + t] = fmaxf(l, 0.f);
                dst[(c0 + 3) * dp + p + t] = fmaxf(h, 0.f);
            }
        }
    }
}

// ---------------- kernel 2: fused eeg dilated stack (8->16->16->16) ----------------
#define EP1 284
#define EP2 284
__global__ void __launch_bounds__(256, 2)
k_eeg_stack(const float* __restrict__ w1, const float* __restrict__ b1,
            const float* __restrict__ w2, const float* __restrict__ b2,
            const float* __restrict__ w3, const float* __restrict__ b3)
{
    __shared__ __align__(16) float sA[16 * EP1];      // l1
    __shared__ __align__(16) float sB[16 * EP2];      // input (8 rows), then l2
    __shared__ __align__(16) float sw1[384], sw2[768], sw3[768];
    __shared__ ull bp1[8], bp2[8], bp3[8];

    int b  = blockIdx.y;
    int t0 = blockIdx.x * 256;
    int tid = threadIdx.x;
    int nOut = min(256, L3_LEN - t0);
    int n2 = nOut + 18, n1 = nOut + 24, nIn = nOut + 26;

    for (int i = tid; i < 384; i += 256) {
        int co = i & 15; int rem = i >> 4; int k = rem % 3; int ci = rem / 3;
        sw1[i] = w1[(co * 8 + ci) * 3 + k];
    }
    for (int i = tid; i < 768; i += 256) {
        int co = i & 15; int rem = i >> 4; int k = rem % 3; int ci = rem / 3;
        sw2[i] = w2[(co * 16 + ci) * 3 + k];
        sw3[i] = w3[(co * 16 + ci) * 3 + k];
    }
    if (tid < 8) {
        bp1[tid] = pk2(b1[2 * tid], b1[2 * tid + 1]);
        bp2[tid] = pk2(b2[2 * tid], b2[2 * tid + 1]);
        bp3[tid] = pk2(b3[2 * tid], b3[2 * tid + 1]);
    }

    const float* inb = g_x0 + ((size_t)b * 8) * TT + t0;
    for (int i = tid; i < 8 * nIn; i += 256) {
        int ci = i / nIn, q = i - ci * nIn;
        sB[ci * EP2 + q] = (t0 + q < TT) ? inb[(size_t)ci * TT + q] : 0.f;
    }
    __syncthreads();

    conv_layer_s<8, 1>(sB, EP2, sA, EP1, sw1, bp1, n1, tid);
    __syncthreads();
    conv_layer_s<16, 3>(sA, EP1, sB, EP2, sw2, bp2, n2, tid);
    __syncthreads();

    // layer3 -> global
    {
        float* ob = g_x3 + ((size_t)b * 16) * TT + t0;
        int items = 4 * ((nOut + 3) >> 2);
        for (int it = tid; it < items; it += 256) {
            int cg = it & 3;
            int p  = (it >> 2) * 4;
            ull b01 = bp3[cg * 2], b23 = bp3[cg * 2 + 1];
            ull a0[4], a1[4];
#pragma unroll
            for (int t = 0; t < 4; t++) { a0[t] = b01; a1[t] = b23; }
#pragma unroll
            for (int ci = 0; ci < 16; ci++) {
#pragma unroll
                for (int k = 0; k < 3; k++) {
                    const ull* wp = (const ull*)&sw3[(ci * 3 + k) * 16 + cg * 4];
                    ull w01 = wp[0], w23 = wp[1];
                    const float* xr = &sB[ci * EP2 + p + k * 9];
#pragma unroll
                    for (int t = 0; t < 4; t++) {
                        ull x2 = pk2(xr[t], xr[t]);
                        fma2(a0[t], w01, x2);
                        fma2(a1[t], w23, x2);
                    }
                }
            }
            float lo[4], hi[4], lo2[4], hi2[4];
#pragma unroll
            for (int t = 0; t < 4; t++) { up2(a0[t], lo[t], hi[t]); up2(a1[t], lo2[t], hi2[t]); }
            int c0 = cg * 4;
            if (p + 3 < nOut) {
                *(float4*)&ob[(size_t)(c0 + 0) * TT + p] =
                    make_float4(fmaxf(lo[0],0.f), fmaxf(lo[1],0.f), fmaxf(lo[2],0.f), fmaxf(lo[3],0.f));
                *(float4*)&ob[(size_t)(c0 + 1) * TT + p] =
                    make_float4(fmaxf(hi[0],0.f), fmaxf(hi[1],0.f), fmaxf(hi[2],0.f), fmaxf(hi[3],0.f));
                *(float4*)&ob[(size_t)(c0 + 2) * TT + p] =
                    make_float4(fmaxf(lo2[0],0.f), fmaxf(lo2[1],0.f), fmaxf(lo2[2],0.f), fmaxf(lo2[3],0.f));
                *(float4*)&ob[(size_t)(c0 + 3) * TT + p] =
                    make_float4(fmaxf(hi2[0],0.f), fmaxf(hi2[1],0.f), fmaxf(hi2[2],0.f), fmaxf(hi2[3],0.f));
            } else {
                for (int t = 0; t < 4; t++) {
                    if (p + t < nOut) {
                        ob[(size_t)(c0 + 0) * TT + p + t] = fmaxf(lo[t],  0.f);
                        ob[(size_t)(c0 + 1) * TT + p + t] = fmaxf(hi[t],  0.f);
                        ob[(size_t)(c0 + 2) * TT + p + t] = fmaxf(lo2[t], 0.f);
                        ob[(size_t)(c0 + 3) * TT + p + t] = fmaxf(hi2[t], 0.f);
                    }
                }
            }
        }
    }
}

// ---------------- kernel 3: eeg row norms ----------------
__global__ void k_eegnorm()
{
    __shared__ float red[256];
    int r = blockIdx.x;
    int tid = threadIdx.x;
    const float* p = g_x3 + (size_t)r * TT;
    float ss = 0.f;
    for (int t = tid; t < L3_LEN; t += 256) { float v = p[t]; ss += v * v; }
    red[tid] = ss; __syncthreads();
    for (int st = 128; st > 0; st >>= 1) {
        if (tid < st) red[tid] += red[tid + st];
        __syncthreads();
    }
    if (tid == 0) g_nx[r] = fmaxf(sqrtf(red[0]), 1e-8f);
}

// ---------------- kernel 4: persistent fused stimulus + cosine + linear ----------------
// grid = 512 (one block per n = s*B+b); block 256. Loops all 32 t-tiles,
// dot/sumsq accumulators live in registers; no global atomics, no finalize kernel.
#define P1 284
#define P2 280
#define P3 260
__global__ void __launch_bounds__(256, 2)
k_stim(const float* __restrict__ stim,
       const float* __restrict__ ws1, const float* __restrict__ bs1,
       const float* __restrict__ ws2, const float* __restrict__ bs2,
       const float* __restrict__ ws3, const float* __restrict__ bs3,
       const float* __restrict__ w_lin, const float* __restrict__ b_lin,
       float* __restrict__ out)
{
    __shared__ __align__(16) float bufA[16 * P1];   // l1 / l3 / partials
    __shared__ __align__(16) float bufB[16 * P2];   // l2 / eeg x
    __shared__ __align__(16) float sh_in[P1];
    __shared__ __align__(16) float sh_w2[768];
    __shared__ __align__(16) float sh_w3[768];
    __shared__ float sh_w1[48];
    __shared__ ull sh_bp2[8], sh_bp3[8];
    __shared__ float sh_b1[16];
    __shared__ float sh_wl[256];

    int n  = blockIdx.x;          // n = s*B + b
    int s  = n >> 6;
    int b  = n & 63;
    int tid = threadIdx.x;

    if (tid < 48) { int co = tid & 15, k = tid >> 4; sh_w1[k * 16 + co] = ws1[co * 3 + k]; }
    for (int i = tid; i < 768; i += 256) {
        int co = i & 15; int rem = i >> 4; int k = rem % 3; int ci = rem / 3;
        sh_w2[i] = ws2[(co * 16 + ci) * 3 + k];
        sh_w3[i] = ws3[(co * 16 + ci) * 3 + k];
    }
    if (tid < 8) {
        sh_bp2[tid] = pk2(bs2[2 * tid], bs2[2 * tid + 1]);
        sh_bp3[tid] = pk2(bs3[2 * tid], bs3[2 * tid + 1]);
    }
    if (tid < 16) sh_b1[tid] = bs1[tid];
    sh_wl[tid] = w_lin[tid];

    const float* seq = stim + ((size_t)(b * SS + s)) * TT;
    const float* xbase = g_x3 + ((size_t)b * 16) * TT;

    // dot-phase thread mapping (fixed across tiles)
    int chunk = tid >> 6;
    int q = tid & 63;
    int ip = q >> 3, jp = q & 7;
    int i0 = ip * 2, j0 = jp * 2;
    const ull* A0 = (const ull*)(bufA + (i0 + 0) * P3);
    const ull* A1 = (const ull*)(bufA + (i0 + 1) * P3);
    const ull* B0 = (const ull*)(bufB + (j0 + 0) * P3);
    const ull* B1 = (const ull*)(bufB + (j0 + 1) * P3);

    ull c00 = 0, c01 = 0, c10 = 0, c11 = 0, ss0 = 0, ss1 = 0;

    for (int tile = 0; tile < 32; tile++) {
        int t0 = tile * 256;
        int nOut = min(256, L3_LEN - t0);
        int n1 = nOut + 24, n2 = nOut + 18, nIn = nOut + 26;

        // stage stimulus tile (writes only sh_in; prior dot phase reads only bufA/bufB)
        for (int i = tid; i < nIn; i += 256) sh_in[i] = seq[t0 + i];
        __syncthreads();   // orders: prev dot reads done (bufA safe) + sh_in ready

        // layer 1: 1 -> 16, dil 1
        for (int it = tid; it < 16 * n1; it += 256) {
            int c = it & 15, qq = it >> 4;
            float acc = sh_b1[c];
            acc += sh_in[qq + 0] * sh_w1[ 0 + c];
            acc += sh_in[qq + 1] * sh_w1[16 + c];
            acc += sh_in[qq + 2] * sh_w1[32 + c];
            bufA[c * P1 + qq] = fmaxf(acc, 0.f);
        }
        __syncthreads();

        // layer 2: 16 -> 16, dil 3
        conv_layer_s<16, 3>(bufA, P1, bufB, P2, sh_w2, sh_bp2, n2, tid);
        __syncthreads();

        // layer 3: 16 -> 16, dil 9
        conv_layer_s<16, 9>(bufB, P2, bufA, P3, sh_w3, sh_bp3, nOut, tid);
        __syncthreads();

        // eeg x tile into bufB (l2 dead)
        {
            const float* xb = xbase + t0;
#pragma unroll
            for (int j = 0; j < 16; j++)
                if (tid < nOut) bufB[j * P3 + tid] = xb[(size_t)j * TT + tid];
        }
        __syncthreads();

        // dot accumulate (registers persist across tiles)
        int tBeg = chunk * 64;
        int tEnd = min(tBeg + 64, nOut);
        for (int t2 = tBeg >> 1; t2 < (tEnd >> 1); t2++) {
            ull a0 = A0[t2], a1 = A1[t2], b0 = B0[t2], b1 = B1[t2];
            fma2(c00, a0, b0); fma2(c01, a0, b1);
            fma2(c10, a1, b0); fma2(c11, a1, b1);
            if (jp == 0) { fma2(ss0, a0, a0); fma2(ss1, a1, a1); }
        }
        // no sync here: next iteration's first sync orders dot-reads vs l1 writes
    }
    __syncthreads();   // all dot reads complete before bufA reuse as partials

    // write partials: dot[chunk][i][j], sumsq[chunk][i]
    {
        float l, h;
        float* part = bufA;
        up2(c00, l, h); part[chunk * 256 + (i0 + 0) * 16 + j0 + 0] = l + h;
        up2(c01, l, h); part[chunk * 256 + (i0 + 0) * 16 + j0 + 1] = l + h;
        up2(c10, l, h); part[chunk * 256 + (i0 + 1) * 16 + j0 + 0] = l + h;
        up2(c11, l, h); part[chunk * 256 + (i0 + 1) * 16 + j0 + 1] = l + h;
        if (jp == 0) {
            up2(ss0, l, h); part[1024 + chunk * 16 + i0 + 0] = l + h;
            up2(ss1, l, h); part[1024 + chunk * 16 + i0 + 1] = l + h;
        }
    }
    __syncthreads();

    // cosine + linear, block reduction
    int i = tid >> 4, j = tid & 15;
    float d  = bufA[tid] + bufA[256 + tid] + bufA[512 + tid] + bufA[768 + tid];
    float s2 = bufA[1024 + i] + bufA[1024 + 16 + i]
             + bufA[1024 + 32 + i] + bufA[1024 + 48 + i];
    float ni = fmaxf(sqrtf(s2), 1e-8f);
    float nj = g_nx[b * 16 + j];
    float v  = sh_wl[tid] * d / (ni * nj);
    __syncthreads();

    float* red = bufA + 2048;
    red[tid] = v; __syncthreads();
    for (int st = 128; st > 0; st >>= 1) {
        if (tid < st) red[tid] += red[tid + st];
        __syncthreads();
    }
    if (tid == 0) out[b * SS + s] = red[0] + b_lin[0];
}

// ---------------- launch ----------------
extern "C" void kernel_launch(void* const* d_in, const int* in_sizes, int n_in,
                              void* d_out, int out_size)
{
    const float* eeg   = (const float*)d_in[0];
    const float* stim  = (const float*)d_in[1];
    const float* w_eeg = (const float*)d_in[2];
    const float* b_eeg = (const float*)d_in[3];
    const float* w_e1  = (const float*)d_in[4];
    const float* b_e1  = (const float*)d_in[5];
    const float* w_e2  = (const float*)d_in[6];
    const float* b_e2  = (const float*)d_in[7];
    const float* w_e3  = (const float*)d_in[8];
    const float* b_e3  = (const float*)d_in[9];
    const float* w_s1  = (const float*)d_in[10];
    const float* b_s1  = (const float*)d_in[11];
    const float* w_s2  = (const float*)d_in[12];
    const float* b_s2  = (const float*)d_in[13];
    const float* w_s3  = (const float*)d_in[14];
    const float* b_s3  = (const float*)d_in[15];
    const float* w_lin = (const float*)d_in[16];
    const float* b_lin = (const float*)d_in[17];
    float* out = (float*)d_out;

    k_head<<<(BB * TT) / 256, 256>>>(eeg, w_eeg, b_eeg);
    k_eeg_stack<<<dim3(32, BB), 256>>>(w_e1, b_e1, w_e2, b_e2, w_e3, b_e3);
    k_eegnorm<<<BB * 16, 256>>>();

    k_stim<<<BB * SS, 256>>>(stim, w_s1, b_s1, w_s2, b_s2, w_s3, b_s3,
                             w_lin, b_lin, out);
}

// round 11
// speedup vs baseline: 1.0281x; 1.0009x over previous
#include <cuda_runtime.h>
#include <cuda_bf16.h>
#include <math.h>

typedef unsigned long long ull;

// ---------------- problem constants ----------------
#define BB 64
#define SS 8
#define TT 8192
#define L1_LEN 8190
#define L2_LEN 8184
#define L3_LEN 8166

// ---------------- packed f32x2 helpers ----------------
__device__ __forceinline__ ull pk2(float lo, float hi) {
    ull r; asm("mov.b64 %0, {%1, %2};" : "=l"(r) : "f"(lo), "f"(hi)); return r;
}
__device__ __forceinline__ void up2(ull v, float& lo, float& hi) {
    asm("mov.b64 {%0, %1}, %2;" : "=f"(lo), "=f"(hi) : "l"(v));
}
__device__ __forceinline__ void fma2(ull& d, ull a, ull b) {
    asm("fma.rn.f32x2 %0, %1, %2, %0;" : "+l"(d) : "l"(a), "l"(b));
}

// ---------------- device scratch ----------------
__device__ float g_x0[(size_t)BB * 8  * TT];   // eeg after 1x1 head
__device__ float g_x3[(size_t)BB * 16 * TT];   // eeg final features
__device__ float g_nx[BB * 16];                // eeg norms (sqrt+clamp)

// ---------------- kernel 1: eeg 1x1 head (64 -> 8) ----------------
__global__ void k_head(const float* __restrict__ eeg,
                       const float* __restrict__ w,      // [8][64]
                       const float* __restrict__ bias)   // [8]
{
    __shared__ float sh_w[512];
    __shared__ float sh_b[8];
    int tid = threadIdx.x;
    for (int i = tid; i < 512; i += 256) sh_w[i] = w[i];
    if (tid < 8) sh_b[tid] = bias[tid];
    __syncthreads();

    size_t idx = (size_t)blockIdx.x * 256 + tid;
    int b = (int)(idx >> 13);
    int t = (int)(idx & (TT - 1));

    const float4* ep = (const float4*)(eeg + idx * 64);
    float acc[8];
#pragma unroll
    for (int c = 0; c < 8; c++) acc[c] = sh_b[c];
#pragma unroll
    for (int q = 0; q < 16; q++) {
        float4 v = ep[q];
#pragma unroll
        for (int c = 0; c < 8; c++) {
            acc[c] += v.x * sh_w[c * 64 + q * 4 + 0]
                    + v.y * sh_w[c * 64 + q * 4 + 1]
                    + v.z * sh_w[c * 64 + q * 4 + 2]
                    + v.w * sh_w[c * 64 + q * 4 + 3];
        }
    }
    float* ob = g_x0 + ((size_t)b * 8) * TT + t;
#pragma unroll
    for (int c = 0; c < 8; c++) ob[(size_t)c * TT] = acc[c];
}

// ---------------- packed conv layer body (shared -> shared) ----------------
template <int CIN, int DIL>
__device__ __forceinline__ void conv_layer_s(const float* __restrict__ src, int sp,
                                             float* __restrict__ dst, int dp,
                                             const float* __restrict__ w,
                                             const ull* __restrict__ bp,
                                             int len, int tid)
{
    int items = 4 * ((len + 3) >> 2);
    for (int it = tid; it < items; it += 256) {
        int cg = it & 3;
        int p  = (it >> 2) * 4;
        ull b01 = bp[cg * 2], b23 = bp[cg * 2 + 1];
        ull a0[4], a1[4];
#pragma unroll
        for (int t = 0; t < 4; t++) { a0[t] = b01; a1[t] = b23; }
#pragma unroll
        for (int ci = 0; ci < CIN; ci++) {
#pragma unroll
            for (int k = 0; k < 3; k++) {
                const ull* wp = (const ull*)&w[(ci * 3 + k) * 16 + cg * 4];
                ull w01 = wp[0], w23 = wp[1];
                const float* xr = &src[ci * sp + p + k * DIL];
#pragma unroll
                for (int t = 0; t < 4; t++) {
                    ull x2 = pk2(xr[t], xr[t]);
                    fma2(a0[t], w01, x2);
                    fma2(a1[t], w23, x2);
                }
            }
        }
        int c0 = cg * 4;
#pragma unroll
        for (int t = 0; t < 4; t++) {
            if (p + t < len) {
                float l, h;
                up2(a0[t], l, h);
                dst[(c0 + 0) * dp + p + t] = fmaxf(l, 0.f);
                dst[(c0 + 1) * dp + p + t] = fmaxf(h, 0.f);
                up2(a1[t], l, h);
                dst[(c0 + 2) * dp + p + t] = fmaxf(l, 0.f);
                dst[(c0 + 3) * dp + p + t] = fmaxf(h, 0.f);
            }
        }
    }
}

// ---------------- kernel 2: fused eeg dilated stack (8->16->16->16) ----------------
#define EP1 284
#define EP2 284
__global__ void __launch_bounds__(256, 2)
k_eeg_stack(const float* __restrict__ w1, const float* __restrict__ b1,
            const float* __restrict__ w2, const float* __restrict__ b2,
            const float* __restrict__ w3, const float* __restrict__ b3)
{
    __shared__ __align__(16) float sA[16 * EP1];      // l1
    __shared__ __align__(16) float sB[16 * EP2];      // input (8 rows), then l2
    __shared__ __align__(16) float sw1[384], sw2[768], sw3[768];
    __shared__ ull bp1[8], bp2[8], bp3[8];

    int b  = blockIdx.y;
    int t0 = blockIdx.x * 256;
    int tid = threadIdx.x;
    int nOut = min(256, L3_LEN - t0);
    int n2 = nOut + 18, n1 = nOut + 24, nIn = nOut + 26;

    for (int i = tid; i < 384; i += 256) {
        int co = i & 15; int rem = i >> 4; int k = rem % 3; int ci = rem / 3;
        sw1[i] = w1[(co * 8 + ci) * 3 + k];
    }
    for (int i = tid; i < 768; i += 256) {
        int co = i & 15; int rem = i >> 4; int k = rem % 3; int ci = rem / 3;
        sw2[i] = w2[(co * 16 + ci) * 3 + k];
        sw3[i] = w3[(co * 16 + ci) * 3 + k];
    }
    if (tid < 8) {
        bp1[tid] = pk2(b1[2 * tid], b1[2 * tid + 1]);
        bp2[tid] = pk2(b2[2 * tid], b2[2 * tid + 1]);
        bp3[tid] = pk2(b3[2 * tid], b3[2 * tid + 1]);
    }

    const float* inb = g_x0 + ((size_t)b * 8) * TT + t0;
    for (int i = tid; i < 8 * nIn; i += 256) {
        int ci = i / nIn, q = i - ci * nIn;
        sB[ci * EP2 + q] = (t0 + q < TT) ? inb[(size_t)ci * TT + q] : 0.f;
    }
    __syncthreads();

    conv_layer_s<8, 1>(sB, EP2, sA, EP1, sw1, bp1, n1, tid);
    __syncthreads();
    conv_layer_s<16, 3>(sA, EP1, sB, EP2, sw2, bp2, n2, tid);
    __syncthreads();

    // layer3 -> global
    {
        float* ob = g_x3 + ((size_t)b * 16) * TT + t0;
        int items = 4 * ((nOut + 3) >> 2);
        for (int it = tid; it < items; it += 256) {
            int cg = it & 3;
            int p  = (it >> 2) * 4;
            ull b01 = bp3[cg * 2], b23 = bp3[cg * 2 + 1];
            ull a0[4], a1[4];
#pragma unroll
            for (int t = 0; t < 4; t++) { a0[t] = b01; a1[t] = b23; }
#pragma unroll
            for (int ci = 0; ci < 16; ci++) {
#pragma unroll
                for (int k = 0; k < 3; k++) {
                    const ull* wp = (const ull*)&sw3[(ci * 3 + k) * 16 + cg * 4];
                    ull w01 = wp[0], w23 = wp[1];
                    const float* xr = &sB[ci * EP2 + p + k * 9];
#pragma unroll
                    for (int t = 0; t < 4; t++) {
                        ull x2 = pk2(xr[t], xr[t]);
                        fma2(a0[t], w01, x2);
                        fma2(a1[t], w23, x2);
                    }
                }
            }
            float lo[4], hi[4], lo2[4], hi2[4];
#pragma unroll
            for (int t = 0; t < 4; t++) { up2(a0[t], lo[t], hi[t]); up2(a1[t], lo2[t], hi2[t]); }
            int c0 = cg * 4;
            if (p + 3 < nOut) {
                *(float4*)&ob[(size_t)(c0 + 0) * TT + p] =
                    make_float4(fmaxf(lo[0],0.f), fmaxf(lo[1],0.f), fmaxf(lo[2],0.f), fmaxf(lo[3],0.f));
                *(float4*)&ob[(size_t)(c0 + 1) * TT + p] =
                    make_float4(fmaxf(hi[0],0.f), fmaxf(hi[1],0.f), fmaxf(hi[2],0.f), fmaxf(hi[3],0.f));
                *(float4*)&ob[(size_t)(c0 + 2) * TT + p] =
                    make_float4(fmaxf(lo2[0],0.f), fmaxf(lo2[1],0.f), fmaxf(lo2[2],0.f), fmaxf(lo2[3],0.f));
                *(float4*)&ob[(size_t)(c0 + 3) * TT + p] =
                    make_float4(fmaxf(hi2[0],0.f), fmaxf(hi2[1],0.f), fmaxf(hi2[2],0.f), fmaxf(hi2[3],0.f));
            } else {
                for (int t = 0; t < 4; t++) {
                    if (p + t < nOut) {
                        ob[(size_t)(c0 + 0) * TT + p + t] = fmaxf(lo[t],  0.f);
                        ob[(size_t)(c0 + 1) * TT + p + t] = fmaxf(hi[t],  0.f);
                        ob[(size_t)(c0 + 2) * TT + p + t] = fmaxf(lo2[t], 0.f);
                        ob[(size_t)(c0 + 3) * TT + p + t] = fmaxf(hi2[t], 0.f);
                    }
                }
            }
        }
    }
}

// ---------------- kernel 3: eeg row norms ----------------
__global__ void k_eegnorm()
{
    __shared__ float red[256];
    int r = blockIdx.x;
    int tid = threadIdx.x;
    const float* p = g_x3 + (size_t)r * TT;
    float ss = 0.f;
    for (int t = tid; t < L3_LEN; t += 256) { float v = p[t]; ss += v * v; }
    red[tid] = ss; __syncthreads();
    for (int st = 128; st > 0; st >>= 1) {
        if (tid < st) red[tid] += red[tid + st];
        __syncthreads();
    }
    if (tid == 0) g_nx[r] = fmaxf(sqrtf(red[0]), 1e-8f);
}

// ---------------- kernel 4: persistent fused stimulus + cosine + linear ----------------
#define P1 284
#define P2 280
#define P3 260
__global__ void __launch_bounds__(256, 2)
k_stim(const float* __restrict__ stim,
       const float* __restrict__ ws1, const float* __restrict__ bs1,
       const float* __restrict__ ws2, const float* __restrict__ bs2,
       const float* __restrict__ ws3, const float* __restrict__ bs3,
       const float* __restrict__ w_lin, const float* __restrict__ b_lin,
       float* __restrict__ out)
{
    __shared__ __align__(16) float bufA[16 * P1];   // l1 / l3 / partials
    __shared__ __align__(16) float bufB[16 * P2];   // l2 / eeg x
    __shared__ __align__(16) float sh_in[P1];
    __shared__ __align__(16) float sh_w2[768];
    __shared__ __align__(16) float sh_w3[768];
    __shared__ float sh_w1[48];
    __shared__ ull sh_bp2[8], sh_bp3[8];
    __shared__ float sh_b1[16];
    __shared__ float sh_wl[256];

    int n  = blockIdx.x;          // n = s*B + b
    int s  = n >> 6;
    int b  = n & 63;
    int tid = threadIdx.x;

    if (tid < 48) { int co = tid & 15, k = tid >> 4; sh_w1[k * 16 + co] = ws1[co * 3 + k]; }
    for (int i = tid; i < 768; i += 256) {
        int co = i & 15; int rem = i >> 4; int k = rem % 3; int ci = rem / 3;
        sh_w2[i] = ws2[(co * 16 + ci) * 3 + k];
        sh_w3[i] = ws3[(co * 16 + ci) * 3 + k];
    }
    if (tid < 8) {
        sh_bp2[tid] = pk2(bs2[2 * tid], bs2[2 * tid + 1]);
        sh_bp3[tid] = pk2(bs3[2 * tid], bs3[2 * tid + 1]);
    }
    if (tid < 16) sh_b1[tid] = bs1[tid];
    sh_wl[tid] = w_lin[tid];

    const float* seq = stim + ((size_t)(b * SS + s)) * TT;
    const float* xbase = g_x3 + ((size_t)b * 16) * TT;

    int chunk = tid >> 6;
    int q = tid & 63;
    int ip = q >> 3, jp = q & 7;
    int i0 = ip * 2, j0 = jp * 2;
    const ull* A0 = (const ull*)(bufA + (i0 + 0) * P3);
    const ull* A1 = (const ull*)(bufA + (i0 + 1) * P3);
    const ull* B0 = (const ull*)(bufB + (j0 + 0) * P3);
    const ull* B1 = (const ull*)(bufB + (j0 + 1) * P3);

    ull c00 = 0, c01 = 0, c10 = 0, c11 = 0, ss0 = 0, ss1 = 0;

    for (int tile = 0; tile < 32; tile++) {
        int t0 = tile * 256;
        int nOut = min(256, L3_LEN - t0);
        int n1 = nOut + 24, n2 = nOut + 18, nIn = nOut + 26;

        for (int i = tid; i < nIn; i += 256) sh_in[i] = seq[t0 + i];
        __syncthreads();   // orders: prev dot reads done (bufA safe) + sh_in ready

        // layer 1: 1 -> 16, dil 1
        for (int it = tid; it < 16 * n1; it += 256) {
            int c = it & 15, qq = it >> 4;
            float acc = sh_b1[c];
            acc += sh_in[qq + 0] * sh_w1[ 0 + c];
            acc += sh_in[qq + 1] * sh_w1[16 + c];
            acc += sh_in[qq + 2] * sh_w1[32 + c];
            bufA[c * P1 + qq] = fmaxf(acc, 0.f);
        }
        __syncthreads();

        conv_layer_s<16, 3>(bufA, P1, bufB, P2, sh_w2, sh_bp2, n2, tid);
        __syncthreads();

        conv_layer_s<16, 9>(bufB, P2, bufA, P3, sh_w3, sh_bp3, nOut, tid);
        __syncthreads();

        {
            const float* xb = xbase + t0;
#pragma unroll
            for (int j = 0; j < 16; j++)
                if (tid < nOut) bufB[j * P3 + tid] = xb[(size_t)j * TT + tid];
        }
        __syncthreads();

        int tBeg = chunk * 64;
        int tEnd = min(tBeg + 64, nOut);
        for (int t2 = tBeg >> 1; t2 < (tEnd >> 1); t2++) {
            ull a0 = A0[t2], a1 = A1[t2], b0 = B0[t2], b1 = B1[t2];
            fma2(c00, a0, b0); fma2(c01, a0, b1);
            fma2(c10, a1, b0); fma2(c11, a1, b1);
            if (jp == 0) { fma2(ss0, a0, a0); fma2(ss1, a1, a1); }
        }
        // no sync: next tile's first sync orders dot-reads vs l1 writes
    }
    __syncthreads();

    {
        float l, h;
        float* part = bufA;
        up2(c00, l, h); part[chunk * 256 + (i0 + 0) * 16 + j0 + 0] = l + h;
        up2(c01, l, h); part[chunk * 256 + (i0 + 0) * 16 + j0 + 1] = l + h;
        up2(c10, l, h); part[chunk * 256 + (i0 + 1) * 16 + j0 + 0] = l + h;
        up2(c11, l, h); part[chunk * 256 + (i0 + 1) * 16 + j0 + 1] = l + h;
        if (jp == 0) {
            up2(ss0, l, h); part[1024 + chunk * 16 + i0 + 0] = l + h;
            up2(ss1, l, h); part[1024 + chunk * 16 + i0 + 1] = l + h;
        }
    }
    __syncthreads();

    int i = tid >> 4, j = tid & 15;
    float d  = bufA[tid] + bufA[256 + tid] + bufA[512 + tid] + bufA[768 + tid];
    float s2 = bufA[1024 + i] + bufA[1024 + 16 + i]
             + bufA[1024 + 32 + i] + bufA[1024 + 48 + i];
    float ni = fmaxf(sqrtf(s2), 1e-8f);
    float nj = g_nx[b * 16 + j];
    float v  = sh_wl[tid] * d / (ni * nj);
    __syncthreads();

    float* red = bufA + 2048;
    red[tid] = v; __syncthreads();
    for (int st = 128; st > 0; st >>= 1) {
        if (tid < st) red[tid] += red[tid + st];
        __syncthreads();
    }
    if (tid == 0) out[b * SS + s] = red[0] + b_lin[0];
}

// ---------------- launch ----------------
extern "C" void kernel_launch(void* const* d_in, const int* in_sizes, int n_in,
                              void* d_out, int out_size)
{
    const float* eeg   = (const float*)d_in[0];
    const float* stim  = (const float*)d_in[1];
    const float* w_eeg = (const float*)d_in[2];
    const float* b_eeg = (const float*)d_in[3];
    const float* w_e1  = (const float*)d_in[4];
    const float* b_e1  = (const float*)d_in[5];
    const float* w_e2  = (const float*)d_in[6];
    const float* b_e2  = (const float*)d_in[7];
    const float* w_e3  = (const float*)d_in[8];
    const float* b_e3  = (const float*)d_in[9];
    const float* w_s1  = (const float*)d_in[10];
    const float* b_s1  = (const float*)d_in[11];
    const float* w_s2  = (const float*)d_in[12];
    const float* b_s2  = (const float*)d_in[13];
    const float* w_s3  = (const float*)d_in[14];
    const float* b_s3  = (const float*)d_in[15];
    const float* w_lin = (const float*)d_in[16];
    const float* b_lin = (const float*)d_in[17];
    float* out = (float*)d_out;

    k_head<<<(BB * TT) / 256, 256>>>(eeg, w_eeg, b_eeg);
    k_eeg_stack<<<dim3(32, BB), 256>>>(w_e1, b_e1, w_e2, b_e2, w_e3, b_e3);
    k_eegnorm<<<BB * 16, 256>>>();

    k_stim<<<BB * SS, 256>>>(stim, w_s1, b_s1, w_s2, b_s2, w_s3, b_s3,
                             w_lin, b_lin, out);
}

// round 12
// speedup vs baseline: 1.0287x; 1.0006x over previous
#include <cuda_runtime.h>
#include <cuda_bf16.h>
#include <math.h>

typedef unsigned long long ull;

// ---------------- problem constants ----------------
#define BB 64
#define SS 8
#define TT 8192
#define L1_LEN 8190
#define L2_LEN 8184
#define L3_LEN 8166

// ---------------- packed f32x2 helpers ----------------
__device__ __forceinline__ ull pk2(float lo, float hi) {
    ull r; asm("mov.b64 %0, {%1, %2};" : "=l"(r) : "f"(lo), "f"(hi)); return r;
}
__device__ __forceinline__ void up2(ull v, float& lo, float& hi) {
    asm("mov.b64 {%0, %1}, %2;" : "=f"(lo), "=f"(hi) : "l"(v));
}
__device__ __forceinline__ void fma2(ull& d, ull a, ull b) {
    asm("fma.rn.f32x2 %0, %1, %2, %0;" : "+l"(d) : "l"(a), "l"(b));
}

// ---------------- device scratch ----------------
__device__ float g_x0[(size_t)BB * 8  * TT];   // eeg after 1x1 head
__device__ float g_x3[(size_t)BB * 16 * TT];   // eeg final features
__device__ float g_nx[BB * 16];                // eeg norms (sqrt+clamp)

// ---------------- kernel 1: eeg 1x1 head (64 -> 8) ----------------
__global__ void k_head(const float* __restrict__ eeg,
                       const float* __restrict__ w,      // [8][64]
                       const float* __restrict__ bias)   // [8]
{
    __shared__ float sh_w[512];
    __shared__ float sh_b[8];
    int tid = threadIdx.x;
    for (int i = tid; i < 512; i += 256) sh_w[i] = w[i];
    if (tid < 8) sh_b[tid] = bias[tid];
    __syncthreads();

    size_t idx = (size_t)blockIdx.x * 256 + tid;
    int b = (int)(idx >> 13);
    int t = (int)(idx & (TT - 1));

    const float4* ep = (const float4*)(eeg + idx * 64);
    float acc[8];
#pragma unroll
    for (int c = 0; c < 8; c++) acc[c] = sh_b[c];
#pragma unroll
    for (int q = 0; q < 16; q++) {
        float4 v = ep[q];
#pragma unroll
        for (int c = 0; c < 8; c++) {
            acc[c] += v.x * sh_w[c * 64 + q * 4 + 0]
                    + v.y * sh_w[c * 64 + q * 4 + 1]
                    + v.z * sh_w[c * 64 + q * 4 + 2]
                    + v.w * sh_w[c * 64 + q * 4 + 3];
        }
    }
    float* ob = g_x0 + ((size_t)b * 8) * TT + t;
#pragma unroll
    for (int c = 0; c < 8; c++) ob[(size_t)c * TT] = acc[c];
}

// ---------------- packed conv layer body (shared -> shared) ----------------
template <int CIN, int DIL>
__device__ __forceinline__ void conv_layer_s(const float* __restrict__ src, int sp,
                                             float* __restrict__ dst, int dp,
                                             const float* __restrict__ w,
                                             const ull* __restrict__ bp,
                                             int len, int tid)
{
    int items = 4 * ((len + 3) >> 2);
    for (int it = tid; it < items; it += 256) {
        int cg = it & 3;
        int p  = (it >> 2) * 4;
        ull b01 = bp[cg * 2], b23 = bp[cg * 2 + 1];
        ull a0[4], a1[4];
#pragma unroll
        for (int t = 0; t < 4; t++) { a0[t] = b01; a1[t] = b23; }
#pragma unroll
        for (int ci = 0; ci < CIN; ci++) {
#pragma unroll
            for (int k = 0; k < 3; k++) {
                const ull* wp = (const ull*)&w[(ci * 3 + k) * 16 + cg * 4];
                ull w01 = wp[0], w23 = wp[1];
                const float* xr = &src[ci * sp + p + k * DIL];
#pragma unroll
                for (int t = 0; t < 4; t++) {
                    ull x2 = pk2(xr[t], xr[t]);
                    fma2(a0[t], w01, x2);
                    fma2(a1[t], w23, x2);
                }
            }
        }
        int c0 = cg * 4;
#pragma unroll
        for (int t = 0; t < 4; t++) {
            if (p + t < len) {
                float l, h;
                up2(a0[t], l, h);
                dst[(c0 + 0) * dp + p + t] = fmaxf(l, 0.f);
                dst[(c0 + 1) * dp + p + t] = fmaxf(h, 0.f);
                up2(a1[t], l, h);
                dst[(c0 + 2) * dp + p + t] = fmaxf(l, 0.f);
                dst[(c0 + 3) * dp + p + t] = fmaxf(h, 0.f);
            }
        }
    }
}

// ---------------- kernel 2: fused eeg dilated stack (8->16->16->16) ----------------
#define EP1 284
#define EP2 284
__global__ void __launch_bounds__(256, 2)
k_eeg_stack(const float* __restrict__ w1, const float* __restrict__ b1,
            const float* __restrict__ w2, const float* __restrict__ b2,
            const float* __restrict__ w3, const float* __restrict__ b3)
{
    __shared__ __align__(16) float sA[16 * EP1];      // l1
    __shared__ __align__(16) float sB[16 * EP2];      // input (8 rows), then l2
    __shared__ __align__(16) float sw1[384], sw2[768], sw3[768];
    __shared__ ull bp1[8], bp2[8], bp3[8];

    int b  = blockIdx.y;
    int t0 = blockIdx.x * 256;
    int tid = threadIdx.x;
    int nOut = min(256, L3_LEN - t0);
    int n2 = nOut + 18, n1 = nOut + 24, nIn = nOut + 26;

    for (int i = tid; i < 384; i += 256) {
        int co = i & 15; int rem = i >> 4; int k = rem % 3; int ci = rem / 3;
        sw1[i] = w1[(co * 8 + ci) * 3 + k];
    }
    for (int i = tid; i < 768; i += 256) {
        int co = i & 15; int rem = i >> 4; int k = rem % 3; int ci = rem / 3;
        sw2[i] = w2[(co * 16 + ci) * 3 + k];
        sw3[i] = w3[(co * 16 + ci) * 3 + k];
    }
    if (tid < 8) {
        bp1[tid] = pk2(b1[2 * tid], b1[2 * tid + 1]);
        bp2[tid] = pk2(b2[2 * tid], b2[2 * tid + 1]);
        bp3[tid] = pk2(b3[2 * tid], b3[2 * tid + 1]);
    }

    const float* inb = g_x0 + ((size_t)b * 8) * TT + t0;
    for (int i = tid; i < 8 * nIn; i += 256) {
        int ci = i / nIn, q = i - ci * nIn;
        sB[ci * EP2 + q] = (t0 + q < TT) ? inb[(size_t)ci * TT + q] : 0.f;
    }
    __syncthreads();

    conv_layer_s<8, 1>(sB, EP2, sA, EP1, sw1, bp1, n1, tid);
    __syncthreads();
    conv_layer_s<16, 3>(sA, EP1, sB, EP2, sw2, bp2, n2, tid);
    __syncthreads();

    // layer3 -> global
    {
        float* ob = g_x3 + ((size_t)b * 16) * TT + t0;
        int items = 4 * ((nOut + 3) >> 2);
        for (int it = tid; it < items; it += 256) {
            int cg = it & 3;
            int p  = (it >> 2) * 4;
            ull b01 = bp3[cg * 2], b23 = bp3[cg * 2 + 1];
            ull a0[4], a1[4];
#pragma unroll
            for (int t = 0; t < 4; t++) { a0[t] = b01; a1[t] = b23; }
#pragma unroll
            for (int ci = 0; ci < 16; ci++) {
#pragma unroll
                for (int k = 0; k < 3; k++) {
                    const ull* wp = (const ull*)&sw3[(ci * 3 + k) * 16 + cg * 4];
                    ull w01 = wp[0], w23 = wp[1];
                    const float* xr = &sB[ci * EP2 + p + k * 9];
#pragma unroll
                    for (int t = 0; t < 4; t++) {
                        ull x2 = pk2(xr[t], xr[t]);
                        fma2(a0[t], w01, x2);
                        fma2(a1[t], w23, x2);
                    }
                }
            }
            float lo[4], hi[4], lo2[4], hi2[4];
#pragma unroll
            for (int t = 0; t < 4; t++) { up2(a0[t], lo[t], hi[t]); up2(a1[t], lo2[t], hi2[t]); }
            int c0 = cg * 4;
            if (p + 3 < nOut) {
                *(float4*)&ob[(size_t)(c0 + 0) * TT + p] =
                    make_float4(fmaxf(lo[0],0.f), fmaxf(lo[1],0.f), fmaxf(lo[2],0.f), fmaxf(lo[3],0.f));
                *(float4*)&ob[(size_t)(c0 + 1) * TT + p] =
                    make_float4(fmaxf(hi[0],0.f), fmaxf(hi[1],0.f), fmaxf(hi[2],0.f), fmaxf(hi[3],0.f));
                *(float4*)&ob[(size_t)(c0 + 2) * TT + p] =
                    make_float4(fmaxf(lo2[0],0.f), fmaxf(lo2[1],0.f), fmaxf(lo2[2],0.f), fmaxf(lo2[3],0.f));
                *(float4*)&ob[(size_t)(c0 + 3) * TT + p] =
                    make_float4(fmaxf(hi2[0],0.f), fmaxf(hi2[1],0.f), fmaxf(hi2[2],0.f), fmaxf(hi2[3],0.f));
            } else {
                for (int t = 0; t < 4; t++) {
                    if (p + t < nOut) {
                        ob[(size_t)(c0 + 0) * TT + p + t] = fmaxf(lo[t],  0.f);
                        ob[(size_t)(c0 + 1) * TT + p + t] = fmaxf(hi[t],  0.f);
                        ob[(size_t)(c0 + 2) * TT + p + t] = fmaxf(lo2[t], 0.f);
                        ob[(size_t)(c0 + 3) * TT + p + t] = fmaxf(hi2[t], 0.f);
                    }
                }
            }
        }
    }
}

// ---------------- kernel 3: eeg row norms ----------------
__global__ void k_eegnorm()
{
    __shared__ float red[256];
    int r = blockIdx.x;
    int tid = threadIdx.x;
    const float* p = g_x3 + (size_t)r * TT;
    float ss = 0.f;
    for (int t = tid; t < L3_LEN; t += 256) { float v = p[t]; ss += v * v; }
    red[tid] = ss; __syncthreads();
    for (int st = 128; st > 0; st >>= 1) {
        if (tid < st) red[tid] += red[tid + st];
        __syncthreads();
    }
    if (tid == 0) g_nx[r] = fmaxf(sqrtf(red[0]), 1e-8f);
}

// ---------------- kernel 4: persistent fused stimulus + cosine + linear ----------------
#define P1 284
#define P2 280
#define P3 260
__global__ void __launch_bounds__(256, 2)
k_stim(const float* __restrict__ stim,
       const float* __restrict__ ws1, const float* __restrict__ bs1,
       const float* __restrict__ ws2, const float* __restrict__ bs2,
       const float* __restrict__ ws3, const float* __restrict__ bs3,
       const float* __restrict__ w_lin, const float* __restrict__ b_lin,
       float* __restrict__ out)
{
    __shared__ __align__(16) float bufA[16 * P1];   // l1 / l3 / partials
    __shared__ __align__(16) float bufB[16 * P2];   // l2 / eeg x
    __shared__ __align__(16) float sh_in[P1];
    __shared__ __align__(16) float sh_w2[768];
    __shared__ __align__(16) float sh_w3[768];
    __shared__ float sh_w1[48];
    __shared__ ull sh_bp2[8], sh_bp3[8];
    __shared__ float sh_b1[16];
    __shared__ float sh_wl[256];

    int n  = blockIdx.x;          // n = s*B + b
    int s  = n >> 6;
    int b  = n & 63;
    int tid = threadIdx.x;

    if (tid < 48) { int co = tid & 15, k = tid >> 4; sh_w1[k * 16 + co] = ws1[co * 3 + k]; }
    for (int i = tid; i < 768; i += 256) {
        int co = i & 15; int rem = i >> 4; int k = rem % 3; int ci = rem / 3;
        sh_w2[i] = ws2[(co * 16 + ci) * 3 + k];
        sh_w3[i] = ws3[(co * 16 + ci) * 3 + k];
    }
    if (tid < 8) {
        sh_bp2[tid] = pk2(bs2[2 * tid], bs2[2 * tid + 1]);
        sh_bp3[tid] = pk2(bs3[2 * tid], bs3[2 * tid + 1]);
    }
    if (tid < 16) sh_b1[tid] = bs1[tid];
    sh_wl[tid] = w_lin[tid];

    const float* seq = stim + ((size_t)(b * SS + s)) * TT;
    const float* xbase = g_x3 + ((size_t)b * 16) * TT;

    int chunk = tid >> 6;
    int q = tid & 63;
    int ip = q >> 3, jp = q & 7;
    int i0 = ip * 2, j0 = jp * 2;
    const ull* A0 = (const ull*)(bufA + (i0 + 0) * P3);
    const ull* A1 = (const ull*)(bufA + (i0 + 1) * P3);
    const ull* B0 = (const ull*)(bufB + (j0 + 0) * P3);
    const ull* B1 = (const ull*)(bufB + (j0 + 1) * P3);

    ull c00 = 0, c01 = 0, c10 = 0, c11 = 0, ss0 = 0, ss1 = 0;

    for (int tile = 0; tile < 32; tile++) {
        int t0 = tile * 256;
        int nOut = min(256, L3_LEN - t0);
        int n1 = nOut + 24, n2 = nOut + 18, nIn = nOut + 26;

        for (int i = tid; i < nIn; i += 256) sh_in[i] = seq[t0 + i];
        __syncthreads();   // orders: prev dot reads done (bufA safe) + sh_in ready

        // layer 1: 1 -> 16, dil 1
        for (int it = tid; it < 16 * n1; it += 256) {
            int c = it & 15, qq = it >> 4;
            float acc = sh_b1[c];
            acc += sh_in[qq + 0] * sh_w1[ 0 + c];
            acc += sh_in[qq + 1] * sh_w1[16 + c];
            acc += sh_in[qq + 2] * sh_w1[32 + c];
            bufA[c * P1 + qq] = fmaxf(acc, 0.f);
        }
        __syncthreads();

        conv_layer_s<16, 3>(bufA, P1, bufB, P2, sh_w2, sh_bp2, n2, tid);
        __syncthreads();

        conv_layer_s<16, 9>(bufB, P2, bufA, P3, sh_w3, sh_bp3, nOut, tid);
        __syncthreads();

        {
            const float* xb = xbase + t0;
#pragma unroll
            for (int j = 0; j < 16; j++)
                if (tid < nOut) bufB[j * P3 + tid] = xb[(size_t)j * TT + tid];
        }
        __syncthreads();

        int tBeg = chunk * 64;
        int tEnd = min(tBeg + 64, nOut);
        for (int t2 = tBeg >> 1; t2 < (tEnd >> 1); t2++) {
            ull a0 = A0[t2], a1 = A1[t2], b0 = B0[t2], b1 = B1[t2];
            fma2(c00, a0, b0); fma2(c01, a0, b1);
            fma2(c10, a1, b0); fma2(c11, a1, b1);
            if (jp == 0) { fma2(ss0, a0, a0); fma2(ss1, a1, a1); }
        }
        // no sync: next tile's first sync orders dot-reads vs l1 writes
    }
    __syncthreads();

    {
        float l, h;
        float* part = bufA;
        up2(c00, l, h); part[chunk * 256 + (i0 + 0) * 16 + j0 + 0] = l + h;
        up2(c01, l, h); part[chunk * 256 + (i0 + 0) * 16 + j0 + 1] = l + h;
        up2(c10, l, h); part[chunk * 256 + (i0 + 1) * 16 + j0 + 0] = l + h;
        up2(c11, l, h); part[chunk * 256 + (i0 + 1) * 16 + j0 + 1] = l + h;
        if (jp == 0) {
            up2(ss0, l, h); part[1024 + chunk * 16 + i0 + 0] = l + h;
            up2(ss1, l, h); part[1024 + chunk * 16 + i0 + 1] = l + h;
        }
    }
    __syncthreads();

    int i = tid >> 4, j = tid & 15;
    float d  = bufA[tid] + bufA[256 + tid] + bufA[512 + tid] + bufA[768 + tid];
    float s2 = bufA[1024 + i] + bufA[1024 + 16 + i]
             + bufA[1024 + 32 + i] + bufA[1024 + 48 + i];
    float ni = fmaxf(sqrtf(s2), 1e-8f);
    float nj = g_nx[b * 16 + j];
    float v  = sh_wl[tid] * d / (ni * nj);
    __syncthreads();

    float* red = bufA + 2048;
    red[tid] = v; __syncthreads();
    for (int st = 128; st > 0; st >>= 1) {
        if (tid < st) red[tid] += red[tid + st];
        __syncthreads();
    }
    if (tid == 0) out[b * SS + s] = red[0] + b_lin[0];
}

// ---------------- launch ----------------
extern "C" void kernel_launch(void* const* d_in, const int* in_sizes, int n_in,
                              void* d_out, int out_size)
{
    const float* eeg   = (const float*)d_in[0];
    const float* stim  = (const float*)d_in[1];
    const float* w_eeg = (const float*)d_in[2];
    const float* b_eeg = (const float*)d_in[3];
    const float* w_e1  = (const float*)d_in[4];
    const float* b_e1  = (const float*)d_in[5];
    const float* w_e2  = (const float*)d_in[6];
    const float* b_e2  = (const float*)d_in[7];
    const float* w_e3  = (const float*)d_in[8];
    const float* b_e3  = (const float*)d_in[9];
    const float* w_s1  = (const float*)d_in[10];
    const float* b_s1  = (const float*)d_in[11];
    const float* w_s2  = (const float*)d_in[12];
    const float* b_s2  = (const float*)d_in[13];
    const float* w_s3  = (const float*)d_in[14];
    const float* b_s3  = (const float*)d_in[15];
    const float* w_lin = (const float*)d_in[16];
    const float* b_lin = (const float*)d_in[17];
    float* out = (float*)d_out;

    k_head<<<(BB * TT) / 256, 256>>>(eeg, w_eeg, b_eeg);
    k_eeg_stack<<<dim3(32, BB), 256>>>(w_e1, b_e1, w_e2, b_e2, w_e3, b_e3);
    k_eegnorm<<<BB * 16, 256>>>();

    k_stim<<<BB * SS, 256>>>(stim, w_s1, b_s1, w_s2, b_s2, w_s3, b_s3,
                             w_lin, b_lin, out);
}

// round 13
// speedup vs baseline: 1.3715x; 1.3332x over previous
#include <cuda_runtime.h>
#include <cuda_bf16.h>
#include <math.h>

typedef unsigned long long ull;

// ---------------- problem constants ----------------
#define BB 64
#define SS 8
#define TT 8192
#define L1_LEN 8190
#define L2_LEN 8184
#define L3_LEN 8166

// ---------------- packed f32x2 helpers ----------------
__device__ __forceinline__ ull pk2(float lo, float hi) {
    ull r; asm("mov.b64 %0, {%1, %2};" : "=l"(r) : "f"(lo), "f"(hi)); return r;
}
__device__ __forceinline__ void up2(ull v, float& lo, float& hi) {
    asm("mov.b64 {%0, %1}, %2;" : "=f"(lo), "=f"(hi) : "l"(v));
}
__device__ __forceinline__ void fma2(ull& d, ull a, ull b) {
    asm("fma.rn.f32x2 %0, %1, %2, %0;" : "+l"(d) : "l"(a), "l"(b));
}

// ---------------- device scratch ----------------
__device__ float g_x0[(size_t)BB * 8  * TT];   // eeg after 1x1 head
__device__ float g_x3[(size_t)BB * 16 * TT];   // eeg final features
__device__ float g_nx[BB * 16];                // eeg norms (sqrt+clamp)

// ---------------- kernel 1: eeg 1x1 head (64 -> 8) ----------------
__global__ void k_head(const float* __restrict__ eeg,
                       const float* __restrict__ w,      // [8][64]
                       const float* __restrict__ bias)   // [8]
{
    __shared__ float sh_w[512];
    __shared__ float sh_b[8];
    int tid = threadIdx.x;
    for (int i = tid; i < 512; i += 256) sh_w[i] = w[i];
    if (tid < 8) sh_b[tid] = bias[tid];
    __syncthreads();

    size_t idx = (size_t)blockIdx.x * 256 + tid;
    int b = (int)(idx >> 13);
    int t = (int)(idx & (TT - 1));

    const float4* ep = (const float4*)(eeg + idx * 64);
    float acc[8];
#pragma unroll
    for (int c = 0; c < 8; c++) acc[c] = sh_b[c];
#pragma unroll
    for (int q = 0; q < 16; q++) {
        float4 v = ep[q];
#pragma unroll
        for (int c = 0; c < 8; c++) {
            acc[c] += v.x * sh_w[c * 64 + q * 4 + 0]
                    + v.y * sh_w[c * 64 + q * 4 + 1]
                    + v.z * sh_w[c * 64 + q * 4 + 2]
                    + v.w * sh_w[c * 64 + q * 4 + 3];
        }
    }
    float* ob = g_x0 + ((size_t)b * 8) * TT + t;
#pragma unroll
    for (int c = 0; c < 8; c++) ob[(size_t)c * TT] = acc[c];
}

// ---------------- packed conv layer body (shared -> shared), NT-thread blocks ----------------
template <int CIN, int DIL, int NT>
__device__ __forceinline__ void conv_layer_s(const float* __restrict__ src, int sp,
                                             float* __restrict__ dst, int dp,
                                             const float* __restrict__ w,
                                             const ull* __restrict__ bp,
                                             int len, int tid)
{
    int items = 4 * ((len + 3) >> 2);
    for (int it = tid; it < items; it += NT) {
        int cg = it & 3;
        int p  = (it >> 2) * 4;
        ull b01 = bp[cg * 2], b23 = bp[cg * 2 + 1];
        ull a0[4], a1[4];
#pragma unroll
        for (int t = 0; t < 4; t++) { a0[t] = b01; a1[t] = b23; }
#pragma unroll
        for (int ci = 0; ci < CIN; ci++) {
#pragma unroll
            for (int k = 0; k < 3; k++) {
                const ull* wp = (const ull*)&w[(ci * 3 + k) * 16 + cg * 4];
                ull w01 = wp[0], w23 = wp[1];
                const float* xr = &src[ci * sp + p + k * DIL];
#pragma unroll
                for (int t = 0; t < 4; t++) {
                    ull x2 = pk2(xr[t], xr[t]);
                    fma2(a0[t], w01, x2);
                    fma2(a1[t], w23, x2);
                }
            }
        }
        int c0 = cg * 4;
#pragma unroll
        for (int t = 0; t < 4; t++) {
            if (p + t < len) {
                float l, h;
                up2(a0[t], l, h);
                dst[(c0 + 0) * dp + p + t] = fmaxf(l, 0.f);
                dst[(c0 + 1) * dp + p + t] = fmaxf(h, 0.f);
                up2(a1[t], l, h);
                dst[(c0 + 2) * dp + p + t] = fmaxf(l, 0.f);
                dst[(c0 + 3) * dp + p + t] = fmaxf(h, 0.f);
            }
        }
    }
}

// ---------------- kernel 2: fused eeg dilated stack (8->16->16->16), 128 threads ----------------
#define EP1 284
#define EP2 284
__global__ void __launch_bounds__(128)
k_eeg_stack(const float* __restrict__ w1, const float* __restrict__ b1,
            const float* __restrict__ w2, const float* __restrict__ b2,
            const float* __restrict__ w3, const float* __restrict__ b3)
{
    __shared__ __align__(16) float sA[16 * EP1];      // l1
    __shared__ __align__(16) float sB[16 * EP2];      // input (8 rows), then l2
    __shared__ __align__(16) float sw1[384], sw2[768], sw3[768];
    __shared__ ull bp1[8], bp2[8], bp3[8];

    int b  = blockIdx.y;
    int t0 = blockIdx.x * 256;
    int tid = threadIdx.x;
    int nOut = min(256, L3_LEN - t0);
    int n2 = nOut + 18, n1 = nOut + 24, nIn = nOut + 26;

    for (int i = tid; i < 384; i += 128) {
        int co = i & 15; int rem = i >> 4; int k = rem % 3; int ci = rem / 3;
        sw1[i] = w1[(co * 8 + ci) * 3 + k];
    }
    for (int i = tid; i < 768; i += 128) {
        int co = i & 15; int rem = i >> 4; int k = rem % 3; int ci = rem / 3;
        sw2[i] = w2[(co * 16 + ci) * 3 + k];
        sw3[i] = w3[(co * 16 + ci) * 3 + k];
    }
    if (tid < 8) {
        bp1[tid] = pk2(b1[2 * tid], b1[2 * tid + 1]);
        bp2[tid] = pk2(b2[2 * tid], b2[2 * tid + 1]);
        bp3[tid] = pk2(b3[2 * tid], b3[2 * tid + 1]);
    }

    const float* inb = g_x0 + ((size_t)b * 8) * TT + t0;
    for (int i = tid; i < 8 * nIn; i += 128) {
        int ci = i / nIn, q = i - ci * nIn;
        sB[ci * EP2 + q] = (t0 + q < TT) ? inb[(size_t)ci * TT + q] : 0.f;
    }
    __syncthreads();

    conv_layer_s<8, 1, 128>(sB, EP2, sA, EP1, sw1, bp1, n1, tid);
    __syncthreads();
    conv_layer_s<16, 3, 128>(sA, EP1, sB, EP2, sw2, bp2, n2, tid);
    __syncthreads();

    // layer3 -> global
    {
        float* ob = g_x3 + ((size_t)b * 16) * TT + t0;
        int items = 4 * ((nOut + 3) >> 2);
        for (int it = tid; it < items; it += 128) {
            int cg = it & 3;
            int p  = (it >> 2) * 4;
            ull b01 = bp3[cg * 2], b23 = bp3[cg * 2 + 1];
            ull a0[4], a1[4];
#pragma unroll
            for (int t = 0; t < 4; t++) { a0[t] = b01; a1[t] = b23; }
#pragma unroll
            for (int ci = 0; ci < 16; ci++) {
#pragma unroll
                for (int k = 0; k < 3; k++) {
                    const ull* wp = (const ull*)&sw3[(ci * 3 + k) * 16 + cg * 4];
                    ull w01 = wp[0], w23 = wp[1];
                    const float* xr = &sB[ci * EP2 + p + k * 9];
#pragma unroll
                    for (int t = 0; t < 4; t++) {
                        ull x2 = pk2(xr[t], xr[t]);
                        fma2(a0[t], w01, x2);
                        fma2(a1[t], w23, x2);
                    }
                }
            }
            float lo[4], hi[4], lo2[4], hi2[4];
#pragma unroll
            for (int t = 0; t < 4; t++) { up2(a0[t], lo[t], hi[t]); up2(a1[t], lo2[t], hi2[t]); }
            int c0 = cg * 4;
            if (p + 3 < nOut) {
                *(float4*)&ob[(size_t)(c0 + 0) * TT + p] =
                    make_float4(fmaxf(lo[0],0.f), fmaxf(lo[1],0.f), fmaxf(lo[2],0.f), fmaxf(lo[3],0.f));
                *(float4*)&ob[(size_t)(c0 + 1) * TT + p] =
                    make_float4(fmaxf(hi[0],0.f), fmaxf(hi[1],0.f), fmaxf(hi[2],0.f), fmaxf(hi[3],0.f));
                *(float4*)&ob[(size_t)(c0 + 2) * TT + p] =
                    make_float4(fmaxf(lo2[0],0.f), fmaxf(lo2[1],0.f), fmaxf(lo2[2],0.f), fmaxf(lo2[3],0.f));
                *(float4*)&ob[(size_t)(c0 + 3) * TT + p] =
                    make_float4(fmaxf(hi2[0],0.f), fmaxf(hi2[1],0.f), fmaxf(hi2[2],0.f), fmaxf(hi2[3],0.f));
            } else {
                for (int t = 0; t < 4; t++) {
                    if (p + t < nOut) {
                        ob[(size_t)(c0 + 0) * TT + p + t] = fmaxf(lo[t],  0.f);
                        ob[(size_t)(c0 + 1) * TT + p + t] = fmaxf(hi[t],  0.f);
                        ob[(size_t)(c0 + 2) * TT + p + t] = fmaxf(lo2[t], 0.f);
                        ob[(size_t)(c0 + 3) * TT + p + t] = fmaxf(hi2[t], 0.f);
                    }
                }
            }
        }
    }
}

// ---------------- kernel 3: eeg row norms ----------------
__global__ void k_eegnorm()
{
    __shared__ float red[256];
    int r = blockIdx.x;
    int tid = threadIdx.x;
    const float* p = g_x3 + (size_t)r * TT;
    float ss = 0.f;
    for (int t = tid; t < L3_LEN; t += 256) { float v = p[t]; ss += v * v; }
    red[tid] = ss; __syncthreads();
    for (int st = 128; st > 0; st >>= 1) {
        if (tid < st) red[tid] += red[tid + st];
        __syncthreads();
    }
    if (tid == 0) g_nx[r] = fmaxf(sqrtf(red[0]), 1e-8f);
}

// ---------------- kernel 4: persistent fused stimulus + cosine + linear, 128 threads ----------------
#define P1 284
#define P2 280
#define P3 260
__global__ void __launch_bounds__(128)
k_stim(const float* __restrict__ stim,
       const float* __restrict__ ws1, const float* __restrict__ bs1,
       const float* __restrict__ ws2, const float* __restrict__ bs2,
       const float* __restrict__ ws3, const float* __restrict__ bs3,
       const float* __restrict__ w_lin, const float* __restrict__ b_lin,
       float* __restrict__ out)
{
    __shared__ __align__(16) float bufA[16 * P1];   // l1 / l3 / partials
    __shared__ __align__(16) float bufB[16 * P2];   // l2 / eeg x
    __shared__ __align__(16) float sh_in[P1];
    __shared__ __align__(16) float sh_w2[768];
    __shared__ __align__(16) float sh_w3[768];
    __shared__ float sh_w1[48];
    __shared__ ull sh_bp2[8], sh_bp3[8];
    __shared__ float sh_b1[16];
    __shared__ float sh_wl[256];

    int n  = blockIdx.x;          // n = s*B + b
    int s  = n >> 6;
    int b  = n & 63;
    int tid = threadIdx.x;

    if (tid < 48) { int co = tid & 15, k = tid >> 4; sh_w1[k * 16 + co] = ws1[co * 3 + k]; }
    for (int i = tid; i < 768; i += 128) {
        int co = i & 15; int rem = i >> 4; int k = rem % 3; int ci = rem / 3;
        sh_w2[i] = ws2[(co * 16 + ci) * 3 + k];
        sh_w3[i] = ws3[(co * 16 + ci) * 3 + k];
    }
    if (tid < 8) {
        sh_bp2[tid] = pk2(bs2[2 * tid], bs2[2 * tid + 1]);
        sh_bp3[tid] = pk2(bs3[2 * tid], bs3[2 * tid + 1]);
    }
    if (tid < 16) sh_b1[tid] = bs1[tid];
    for (int i = tid; i < 256; i += 128) sh_wl[i] = w_lin[i];

    const float* seq = stim + ((size_t)(b * SS + s)) * TT;
    const float* xbase = g_x3 + ((size_t)b * 16) * TT;

    // dot-phase mapping: 128 threads = 2 chunks x 64 (i,j)-pairs (2x2 tiles)
    int chunk = tid >> 6;              // 0..1, each covers 128 t-points
    int q = tid & 63;
    int ip = q >> 3, jp = q & 7;
    int i0 = ip * 2, j0 = jp * 2;
    const ull* A0 = (const ull*)(bufA + (i0 + 0) * P3);
    const ull* A1 = (const ull*)(bufA + (i0 + 1) * P3);
    const ull* B0 = (const ull*)(bufB + (j0 + 0) * P3);
    const ull* B1 = (const ull*)(bufB + (j0 + 1) * P3);

    ull c00 = 0, c01 = 0, c10 = 0, c11 = 0, ss0 = 0, ss1 = 0;

    for (int tile = 0; tile < 32; tile++) {
        int t0 = tile * 256;
        int nOut = min(256, L3_LEN - t0);
        int n1 = nOut + 24, n2 = nOut + 18, nIn = nOut + 26;

        // stage stimulus tile (writes only sh_in; prior dot reads only bufA/bufB)
        for (int i = tid; i < nIn; i += 128) sh_in[i] = seq[t0 + i];
        __syncthreads();   // ends prev dot (bufA/bufB safe) + sh_in ready

        // layer 1: 1 -> 16, dil 1
        for (int it = tid; it < 16 * n1; it += 128) {
            int c = it & 15, qq = it >> 4;
            float acc = sh_b1[c];
            acc += sh_in[qq + 0] * sh_w1[ 0 + c];
            acc += sh_in[qq + 1] * sh_w1[16 + c];
            acc += sh_in[qq + 2] * sh_w1[32 + c];
            bufA[c * P1 + qq] = fmaxf(acc, 0.f);
        }
        __syncthreads();

        conv_layer_s<16, 3, 128>(bufA, P1, bufB, P2, sh_w2, sh_bp2, n2, tid);
        __syncthreads();

        conv_layer_s<16, 9, 128>(bufB, P2, bufA, P3, sh_w3, sh_bp3, nOut, tid);
        __syncthreads();

        // eeg x tile into bufB (l2 dead)
        for (int i = tid; i < 16 * 256; i += 128) {
            int j = i >> 8, t = i & 255;
            if (t < nOut) bufB[j * P3 + t] = xbase[(size_t)j * TT + t0 + t];
        }
        __syncthreads();

        // dot accumulate (registers persist across tiles)
        int tBeg = chunk * 128;
        int tEnd = min(tBeg + 128, nOut);
        for (int t2 = tBeg >> 1; t2 < (tEnd >> 1); t2++) {
            ull a0 = A0[t2], a1 = A1[t2], b0 = B0[t2], b1 = B1[t2];
            fma2(c00, a0, b0); fma2(c01, a0, b1);
            fma2(c10, a1, b0); fma2(c11, a1, b1);
            if (jp == 0) { fma2(ss0, a0, a0); fma2(ss1, a1, a1); }
        }
        // no sync: next tile's first sync orders dot-reads vs l1 writes
    }
    __syncthreads();   // all dot reads complete before bufA reuse as partials

    // partials: dot[chunk][i][j] at [0,512), sumsq[chunk][i] at [512,544)
    {
        float l, h;
        float* part = bufA;
        up2(c00, l, h); part[chunk * 256 + (i0 + 0) * 16 + j0 + 0] = l + h;
        up2(c01, l, h); part[chunk * 256 + (i0 + 0) * 16 + j0 + 1] = l + h;
        up2(c10, l, h); part[chunk * 256 + (i0 + 1) * 16 + j0 + 0] = l + h;
        up2(c11, l, h); part[chunk * 256 + (i0 + 1) * 16 + j0 + 1] = l + h;
        if (jp == 0) {
            up2(ss0, l, h); part[512 + chunk * 16 + i0 + 0] = l + h;
            up2(ss1, l, h); part[512 + chunk * 16 + i0 + 1] = l + h;
        }
    }
    __syncthreads();

    // cosine + linear; each thread covers e = tid, tid+128
    float vsum = 0.f;
#pragma unroll
    for (int r = 0; r < 2; r++) {
        int e = tid + r * 128;
        int i = e >> 4, j = e & 15;
        float d  = bufA[e] + bufA[256 + e];
        float s2 = bufA[512 + i] + bufA[512 + 16 + i];
        float ni = fmaxf(sqrtf(s2), 1e-8f);
        float nj = g_nx[b * 16 + j];
        vsum += sh_wl[e] * d / (ni * nj);
    }
    __syncthreads();

    float* red = bufA + 1024;
    red[tid] = vsum; __syncthreads();
    for (int st = 64; st > 0; st >>= 1) {
        if (tid < st) red[tid] += red[tid + st];
        __syncthreads();
    }
    if (tid == 0) out[b * SS + s] = red[0] + b_lin[0];
}

// ---------------- launch ----------------
extern "C" void kernel_launch(void* const* d_in, const int* in_sizes, int n_in,
                              void* d_out, int out_size)
{
    const float* eeg   = (const float*)d_in[0];
    const float* stim  = (const float*)d_in[1];
    const float* w_eeg = (const float*)d_in[2];
    const float* b_eeg = (const float*)d_in[3];
    const float* w_e1  = (const float*)d_in[4];
    const float* b_e1  = (const float*)d_in[5];
    const float* w_e2  = (const float*)d_in[6];
    const float* b_e2  = (const float*)d_in[7];
    const float* w_e3  = (const float*)d_in[8];
    const float* b_e3  = (const float*)d_in[9];
    const float* w_s1  = (const float*)d_in[10];
    const float* b_s1  = (const float*)d_in[11];
    const float* w_s2  = (const float*)d_in[12];
    const float* b_s2  = (const float*)d_in[13];
    const float* w_s3  = (const float*)d_in[14];
    const float* b_s3  = (const float*)d_in[15];
    const float* w_lin = (const float*)d_in[16];
    const float* b_lin = (const float*)d_in[17];
    float* out = (float*)d_out;

    k_head<<<(BB * TT) / 256, 256>>>(eeg, w_eeg, b_eeg);
    k_eeg_stack<<<dim3(32, BB), 128>>>(w_e1, b_e1, w_e2, b_e2, w_e3, b_e3);
    k_eegnorm<<<BB * 16, 256>>>();

    k_stim<<<BB * SS, 128>>>(stim, w_s1, b_s1, w_s2, b_s2, w_s3, b_s3,
                             w_lin, b_lin, out);
}